// round 2
// baseline (speedup 1.0000x reference)
#include <cuda_runtime.h>
#include <math.h>

#define BN   4
#define CC   256
#define NN   4096
#define DD   32
#define INCH 512

#define PS_LD 68
#define VS_LD 257
#define OB_LD 65
// dynamic smem: qs 2048 + ks 2048 + Ps 64*68 + max(64*257, 256*65)=16640 floats
#define SM2_FLOATS (2048 + 2048 + 64*PS_LD + 16640)
#define SM2_BYTES  (SM2_FLOATS * 4)

__device__ float g_q[BN * DD * NN];
__device__ float g_k[BN * DD * NN];
__device__ float g_v[(size_t)BN * CC * NN];
__device__ float g_rmax[BN * NN];
__device__ float g_rinv[BN * NN];

// ---------------------------------------------------------------------------
// 1x1 conv projection: out[b,o,m] = sum_c W[o,c]*x[b,c,m] + bias[o]
// x = concat(x1, x2) over channels (c < C1 -> x1, else x2).
// Tile: 32 out-ch x 128 pixels, BK=16. 256 threads, 4x4 micro-tile.
// ---------------------------------------------------------------------------
__global__ __launch_bounds__(256) void proj_kernel(
    const float* __restrict__ x1, const float* __restrict__ x2,
    int C1, int Ctot,
    const float* __restrict__ W, const float* __restrict__ bias,
    float* __restrict__ out, int O)
{
    __shared__ float Xs[16][128];
    __shared__ float Ws[16][32];
    const int m0 = blockIdx.x * 128;
    const int o0 = blockIdx.y * 32;
    const int b  = blockIdx.z;
    const int t  = threadIdx.x;
    const int tm = t & 31;   // pixel group (4 pixels)
    const int to = t >> 5;   // out-ch group (4 out-ch), 0..7

    float acc[4][4];
#pragma unroll
    for (int i = 0; i < 4; i++)
#pragma unroll
        for (int j = 0; j < 4; j++) acc[i][j] = 0.f;

    for (int c0 = 0; c0 < Ctot; c0 += 16) {
#pragma unroll
        for (int i = 0; i < 2; i++) {
            int idx = i * 256 + t;
            int r   = idx >> 5;      // 0..15 (channel within tile)
            int c4  = idx & 31;      // float4 index within 128 pixels
            int c   = c0 + r;
            const float* src = (c < C1)
                ? x1 + ((size_t)b * C1 + c) * NN
                : x2 + ((size_t)b * (Ctot - C1) + (c - C1)) * NN;
            *(float4*)&Xs[r][c4 * 4] = *(const float4*)&src[m0 + c4 * 4];
            // weight tile (transposed): Ws[kk][oo] = W[o0+oo][c0+kk]
            int kk = idx >> 5;
            int oo = idx & 31;
            Ws[kk][oo] = W[(size_t)(o0 + oo) * Ctot + c0 + kk];
        }
        __syncthreads();
#pragma unroll
        for (int kk = 0; kk < 16; kk++) {
            float4 xv = *(float4*)&Xs[kk][tm * 4];
            float4 wv = *(float4*)&Ws[kk][to * 4];
            acc[0][0] += wv.x * xv.x; acc[0][1] += wv.x * xv.y;
            acc[0][2] += wv.x * xv.z; acc[0][3] += wv.x * xv.w;
            acc[1][0] += wv.y * xv.x; acc[1][1] += wv.y * xv.y;
            acc[1][2] += wv.y * xv.z; acc[1][3] += wv.y * xv.w;
            acc[2][0] += wv.z * xv.x; acc[2][1] += wv.z * xv.y;
            acc[2][2] += wv.z * xv.z; acc[2][3] += wv.z * xv.w;
            acc[3][0] += wv.w * xv.x; acc[3][1] += wv.w * xv.y;
            acc[3][2] += wv.w * xv.z; acc[3][3] += wv.w * xv.w;
        }
        __syncthreads();
    }
#pragma unroll
    for (int oo = 0; oo < 4; oo++) {
        int o = o0 + to * 4 + oo;
        float bv = bias[o];
        float4 r4 = make_float4(acc[oo][0] + bv, acc[oo][1] + bv,
                                acc[oo][2] + bv, acc[oo][3] + bv);
        *(float4*)&out[((size_t)b * O + o) * NN + m0 + tm * 4] = r4;
    }
}

// ---------------------------------------------------------------------------
// Pass 1: per-row softmax stats (running max + sum of exp) over all N keys.
// Block: 64 query rows; thread (r = t>>2) owns row, (qq = t&3) owns a quarter
// of the columns of each 64-wide key tile. Quarters combined via shfl at end.
// ---------------------------------------------------------------------------
__global__ __launch_bounds__(256) void softmax_stats_kernel()
{
    __shared__ float qs[DD * 64];
    __shared__ float ks[DD * 64];
    const int m0 = blockIdx.x * 64;
    const int b  = blockIdx.y;
    const int t  = threadIdx.x;

#pragma unroll
    for (int i = 0; i < 8; i++) {
        int idx = i * 256 + t;
        int d = idx >> 6, m = idx & 63;
        qs[idx] = g_q[((size_t)b * DD + d) * NN + m0 + m];
    }
    __syncthreads();

    const int r  = t >> 2;
    const int qq = t & 3;
    float qreg[DD];
#pragma unroll
    for (int d = 0; d < DD; d++) qreg[d] = qs[d * 64 + r];

    float run_m = -1e30f, run_s = 0.f;

    for (int n0 = 0; n0 < NN; n0 += 64) {
#pragma unroll
        for (int i = 0; i < 8; i++) {
            int idx = i * 256 + t;
            int d = idx >> 6, n = idx & 63;
            ks[idx] = g_k[((size_t)b * DD + d) * NN + n0 + n];
        }
        __syncthreads();
#pragma unroll
        for (int ch = 0; ch < 4; ch++) {
            int n = qq * 16 + ch * 4;
            float4 s4 = make_float4(0.f, 0.f, 0.f, 0.f);
#pragma unroll
            for (int d = 0; d < DD; d++) {
                float4 kv = *(float4*)&ks[d * 64 + n];
                float qv = qreg[d];
                s4.x += qv * kv.x; s4.y += qv * kv.y;
                s4.z += qv * kv.z; s4.w += qv * kv.w;
            }
            float tmx = fmaxf(fmaxf(s4.x, s4.y), fmaxf(s4.z, s4.w));
            if (tmx > run_m) { run_s *= __expf(run_m - tmx); run_m = tmx; }
            run_s += __expf(s4.x - run_m) + __expf(s4.y - run_m)
                   + __expf(s4.z - run_m) + __expf(s4.w - run_m);
        }
        __syncthreads();
    }
    // combine the 4 quarter-states (lanes r*4 + qq are consecutive)
#pragma unroll
    for (int off = 1; off <= 2; off <<= 1) {
        float om = __shfl_xor_sync(0xffffffffu, run_m, off);
        float os = __shfl_xor_sync(0xffffffffu, run_s, off);
        float nm = fmaxf(run_m, om);
        run_s = run_s * __expf(run_m - nm) + os * __expf(om - nm);
        run_m = nm;
    }
    if (qq == 0) {
        g_rmax[(size_t)b * NN + m0 + r] = run_m;
        g_rinv[(size_t)b * NN + m0 + r] = 1.f / run_s;
    }
}

// ---------------------------------------------------------------------------
// Pass 2: out[b,c,m] = gamma * sum_n P[m,n] * v[c,n] + ef[b,c,m]
// Block: 64 query rows x all 256 channels. Per 64-wide key tile: recompute S,
// normalize with pass-1 stats, then rank-1 accumulate into acc[4][16]/thread.
// ---------------------------------------------------------------------------
__global__ __launch_bounds__(256) void attn_out_kernel(
    const float* __restrict__ ef, const float* __restrict__ gamma_p,
    float* __restrict__ out)
{
    extern __shared__ float smd[];
    float* qs = smd;                       // 2048
    float* ks = smd + 2048;                // 2048
    float* Ps = smd + 4096;                // 64*PS_LD
    float* vs = smd + 4096 + 64 * PS_LD;   // 16640 (aliased as obuf at end)
    __shared__ float rm[64], ri[64];

    const int m0 = blockIdx.x * 64;
    const int b  = blockIdx.y;
    const int t  = threadIdx.x;

#pragma unroll
    for (int i = 0; i < 8; i++) {
        int idx = i * 256 + t;
        int d = idx >> 6, m = idx & 63;
        qs[idx] = g_q[((size_t)b * DD + d) * NN + m0 + m];
    }
    if (t < 64) {
        rm[t] = g_rmax[(size_t)b * NN + m0 + t];
        ri[t] = g_rinv[(size_t)b * NN + m0 + t];
    }
    __syncthreads();

    const int bq = t >> 4;   // 0..15 : m-group (4 rows)
    const int aa = t & 15;   // n-group for S / c-group for PV

    float acc[4][16];
#pragma unroll
    for (int i = 0; i < 4; i++)
#pragma unroll
        for (int j = 0; j < 16; j++) acc[i][j] = 0.f;

    for (int n0 = 0; n0 < NN; n0 += 64) {
#pragma unroll
        for (int i = 0; i < 8; i++) {
            int idx = i * 256 + t;
            int d = idx >> 6, n = idx & 63;
            ks[idx] = g_k[((size_t)b * DD + d) * NN + n0 + n];
        }
        // v tile transposed into vs[n][c] (row stride 257 -> conflict-free)
#pragma unroll 8
        for (int i = 0; i < 64; i++) {
            int idx = i * 256 + t;
            int c = idx >> 6, nn = idx & 63;
            vs[nn * VS_LD + c] = g_v[((size_t)b * CC + c) * NN + n0 + nn];
        }
        __syncthreads();
        // scores S[m][n], 4x4 micro-tile per thread
        {
            int m4 = bq * 4, n4 = aa * 4;
            float s[4][4];
#pragma unroll
            for (int i = 0; i < 4; i++)
#pragma unroll
                for (int j = 0; j < 4; j++) s[i][j] = 0.f;
#pragma unroll
            for (int d = 0; d < DD; d++) {
                float4 q4 = *(float4*)&qs[d * 64 + m4];
                float4 k4 = *(float4*)&ks[d * 64 + n4];
                s[0][0] += q4.x * k4.x; s[0][1] += q4.x * k4.y;
                s[0][2] += q4.x * k4.z; s[0][3] += q4.x * k4.w;
                s[1][0] += q4.y * k4.x; s[1][1] += q4.y * k4.y;
                s[1][2] += q4.y * k4.z; s[1][3] += q4.y * k4.w;
                s[2][0] += q4.z * k4.x; s[2][1] += q4.z * k4.y;
                s[2][2] += q4.z * k4.z; s[2][3] += q4.z * k4.w;
                s[3][0] += q4.w * k4.x; s[3][1] += q4.w * k4.y;
                s[3][2] += q4.w * k4.z; s[3][3] += q4.w * k4.w;
            }
#pragma unroll
            for (int mm = 0; mm < 4; mm++)
                *(float4*)&Ps[(m4 + mm) * PS_LD + n4] =
                    make_float4(s[mm][0], s[mm][1], s[mm][2], s[mm][3]);
        }
        __syncthreads();
        // normalize: P = exp(S - rowmax) * rowinv
#pragma unroll
        for (int i = 0; i < 16; i++) {
            int idx = i * 256 + t;
            int m = idx >> 6, n = idx & 63;
            Ps[m * PS_LD + n] = __expf(Ps[m * PS_LD + n] - rm[m]) * ri[m];
        }
        __syncthreads();
        // PV accumulate: acc[mm][j] += P[m][n] * v[c][n]
#pragma unroll 2
        for (int n = 0; n < 64; n++) {
            float p0 = Ps[(bq * 4 + 0) * PS_LD + n];
            float p1 = Ps[(bq * 4 + 1) * PS_LD + n];
            float p2 = Ps[(bq * 4 + 2) * PS_LD + n];
            float p3 = Ps[(bq * 4 + 3) * PS_LD + n];
            int vb = n * VS_LD + aa;
#pragma unroll
            for (int j = 0; j < 16; j++) {
                float v = vs[vb + j * 16];
                acc[0][j] += p0 * v;
                acc[1][j] += p1 * v;
                acc[2][j] += p2 * v;
                acc[3][j] += p3 * v;
            }
        }
        __syncthreads();
    }

    // epilogue: stage into smem (reuse vs as obuf[c][m], stride 65) for
    // coalesced global writes, then out = gamma*acc + ef.
    float gma = gamma_p[0];
#pragma unroll
    for (int j = 0; j < 16; j++) {
        int c = aa + 16 * j;
#pragma unroll
        for (int mm = 0; mm < 4; mm++)
            vs[c * OB_LD + bq * 4 + mm] = acc[mm][j];
    }
    __syncthreads();
#pragma unroll 8
    for (int i = 0; i < 64; i++) {
        int idx = i * 256 + t;
        int c = idx >> 6, m = idx & 63;
        size_t gi = ((size_t)b * CC + c) * NN + m0 + m;
        out[gi] = gma * vs[c * OB_LD + m] + ef[gi];
    }
}

// ---------------------------------------------------------------------------
extern "C" void kernel_launch(void* const* d_in, const int* in_sizes, int n_in,
                              void* d_out, int out_size)
{
    const float* ef = (const float*)d_in[0];
    const float* sf = (const float*)d_in[1];
    const float* At = (const float*)d_in[2];
    const float* Qw = (const float*)d_in[3];
    const float* Qb = (const float*)d_in[4];
    const float* Kw = (const float*)d_in[5];
    const float* Kb = (const float*)d_in[6];
    const float* Vw = (const float*)d_in[7];
    const float* Vb = (const float*)d_in[8];
    const float* gm = (const float*)d_in[9];
    float* out = (float*)d_out;

    float *qp, *kp, *vp;
    cudaGetSymbolAddress((void**)&qp, g_q);
    cudaGetSymbolAddress((void**)&kp, g_k);
    cudaGetSymbolAddress((void**)&vp, g_v);

    cudaFuncSetAttribute(attn_out_kernel,
                         cudaFuncAttributeMaxDynamicSharedMemorySize, SM2_BYTES);

    // projections: q [B,32,N], k [B,32,N], v [B,256,N]
    proj_kernel<<<dim3(NN / 128, DD / 32, BN), 256>>>(ef, sf, CC, INCH, Qw, Qb, qp, DD);
    proj_kernel<<<dim3(NN / 128, DD / 32, BN), 256>>>(At, At, CC, CC,  Kw, Kb, kp, DD);
    proj_kernel<<<dim3(NN / 128, CC / 32, BN), 256>>>(ef, sf, CC, INCH, Vw, Vb, vp, CC);

    softmax_stats_kernel<<<dim3(NN / 64, BN), 256>>>();
    attn_out_kernel<<<dim3(NN / 64, BN), 256, SM2_BYTES>>>(ef, gm, out);
}

// round 4
// speedup vs baseline: 1.7583x; 1.7583x over previous
#include <cuda_runtime.h>
#include <math.h>

#define BN   4
#define CC   256
#define NN   4096
#define DD   32
#define INCH 512

#define LDK   68   // ks row stride (floats), 16B-aligned rows
#define LDPS  68   // Ps row stride (floats)
#define LDVR  260  // vs row stride (floats): 256 data + 4 pad
#define SMF   (2048 + 32*LDK + 64*LDPS + 64*LDVR)   // 25216 floats
#define SMB   (SMF * 4)                             // 100864 bytes

typedef unsigned long long ull;

__device__ float g_q[BN * DD * NN];
__device__ float g_k[BN * DD * NN];
__device__ float g_vp[(size_t)BN * NN * CC];   // [b][token][channel] interleaved

// ---- packed f32x2 helpers (FFMA2 — only reachable via PTX) --------------
__device__ __forceinline__ ull dup2(float x) {
    ull r; unsigned u = __float_as_uint(x);
    asm("mov.b64 %0, {%1, %1};" : "=l"(r) : "r"(u));
    return r;
}
__device__ __forceinline__ void fma2(ull& acc, ull a, ull b) {
    asm("fma.rn.f32x2 %0, %1, %2, %0;" : "+l"(acc) : "l"(a), "l"(b));
}
__device__ __forceinline__ void add2(ull& acc, ull b) {
    asm("add.rn.f32x2 %0, %1, %0;" : "+l"(acc) : "l"(b));
}
__device__ __forceinline__ float2 unpk(ull v) {
    unsigned lo, hi;
    asm("mov.b64 {%0, %1}, %2;" : "=r"(lo), "=r"(hi) : "l"(v));
    return make_float2(__uint_as_float(lo), __uint_as_float(hi));
}

// ---------------------------------------------------------------------------
// 1x1 conv (scalar) for Q and K: out[b,o,m] = sum_c W[o,c]*x[b,c,m] + bias[o]
// ---------------------------------------------------------------------------
__global__ __launch_bounds__(256) void proj_kernel(
    const float* __restrict__ x1, const float* __restrict__ x2,
    int C1, int Ctot,
    const float* __restrict__ W, const float* __restrict__ bias,
    float* __restrict__ out, int O)
{
    __shared__ float Xs[16][128];
    __shared__ float Ws[16][32];
    const int m0 = blockIdx.x * 128;
    const int o0 = blockIdx.y * 32;
    const int b  = blockIdx.z;
    const int t  = threadIdx.x;
    const int tm = t & 31;
    const int to = t >> 5;

    float acc[4][4];
#pragma unroll
    for (int i = 0; i < 4; i++)
#pragma unroll
        for (int j = 0; j < 4; j++) acc[i][j] = 0.f;

    for (int c0 = 0; c0 < Ctot; c0 += 16) {
#pragma unroll
        for (int i = 0; i < 2; i++) {
            int idx = i * 256 + t;
            int r   = idx >> 5;
            int c4  = idx & 31;
            int c   = c0 + r;
            const float* src = (c < C1)
                ? x1 + ((size_t)b * C1 + c) * NN
                : x2 + ((size_t)b * (Ctot - C1) + (c - C1)) * NN;
            *(float4*)&Xs[r][c4 * 4] = *(const float4*)&src[m0 + c4 * 4];
            int kk = idx >> 5;
            int oo = idx & 31;
            Ws[kk][oo] = W[(size_t)(o0 + oo) * Ctot + c0 + kk];
        }
        __syncthreads();
#pragma unroll
        for (int kk = 0; kk < 16; kk++) {
            float4 xv = *(float4*)&Xs[kk][tm * 4];
            float4 wv = *(float4*)&Ws[kk][to * 4];
            acc[0][0] += wv.x * xv.x; acc[0][1] += wv.x * xv.y;
            acc[0][2] += wv.x * xv.z; acc[0][3] += wv.x * xv.w;
            acc[1][0] += wv.y * xv.x; acc[1][1] += wv.y * xv.y;
            acc[1][2] += wv.y * xv.z; acc[1][3] += wv.y * xv.w;
            acc[2][0] += wv.z * xv.x; acc[2][1] += wv.z * xv.y;
            acc[2][2] += wv.z * xv.z; acc[2][3] += wv.z * xv.w;
            acc[3][0] += wv.w * xv.x; acc[3][1] += wv.w * xv.y;
            acc[3][2] += wv.w * xv.z; acc[3][3] += wv.w * xv.w;
        }
        __syncthreads();
    }
#pragma unroll
    for (int oo = 0; oo < 4; oo++) {
        int o = o0 + to * 4 + oo;
        float bv = bias[o];
        float4 r4 = make_float4(acc[oo][0] + bv, acc[oo][1] + bv,
                                acc[oo][2] + bv, acc[oo][3] + bv);
        *(float4*)&out[((size_t)b * O + o) * NN + m0 + tm * 4] = r4;
    }
}

// ---------------------------------------------------------------------------
// V projection, f32x2-packed over output-channel pairs; writes token-major
// interleaved layout g_vp[b][m][c] so channel pairs are contiguous for PV.
// ---------------------------------------------------------------------------
__global__ __launch_bounds__(256) void projV_kernel(
    const float* __restrict__ x1, const float* __restrict__ x2,
    const float* __restrict__ W, const float* __restrict__ bias)
{
    __shared__ float Xs[16][128];
    __shared__ float Ws[16][32];
    const int m0 = blockIdx.x * 128;
    const int o0 = blockIdx.y * 32;
    const int b  = blockIdx.z;
    const int t  = threadIdx.x;
    const int tm = t & 31;
    const int to = t >> 5;

    ull acc[2][4];
#pragma unroll
    for (int i = 0; i < 2; i++)
#pragma unroll
        for (int j = 0; j < 4; j++) acc[i][j] = 0ULL;

    for (int c0 = 0; c0 < INCH; c0 += 16) {
#pragma unroll
        for (int i = 0; i < 2; i++) {
            int idx = i * 256 + t;
            int r   = idx >> 5;
            int c4  = idx & 31;
            int c   = c0 + r;
            const float* src = (c < CC)
                ? x1 + ((size_t)b * CC + c) * NN
                : x2 + ((size_t)b * CC + (c - CC)) * NN;
            *(float4*)&Xs[r][c4 * 4] = *(const float4*)&src[m0 + c4 * 4];
            int kk = idx >> 5;
            int oo = idx & 31;
            Ws[kk][oo] = W[(size_t)(o0 + oo) * INCH + c0 + kk];
        }
        __syncthreads();
#pragma unroll
        for (int kk = 0; kk < 16; kk++) {
            float4 xv = *(float4*)&Xs[kk][tm * 4];
            ull xd0 = dup2(xv.x), xd1 = dup2(xv.y);
            ull xd2 = dup2(xv.z), xd3 = dup2(xv.w);
            ull w0 = *(const ull*)&Ws[kk][to * 4];
            ull w1 = *(const ull*)&Ws[kk][to * 4 + 2];
            fma2(acc[0][0], w0, xd0); fma2(acc[0][1], w0, xd1);
            fma2(acc[0][2], w0, xd2); fma2(acc[0][3], w0, xd3);
            fma2(acc[1][0], w1, xd0); fma2(acc[1][1], w1, xd1);
            fma2(acc[1][2], w1, xd2); fma2(acc[1][3], w1, xd3);
        }
        __syncthreads();
    }
#pragma unroll
    for (int op = 0; op < 2; op++) {
        int o = o0 + to * 4 + 2 * op;
        ull b2 = *(const ull*)&bias[o];
#pragma unroll
        for (int px = 0; px < 4; px++) {
            add2(acc[op][px], b2);
            int m = m0 + tm * 4 + px;
            *(ull*)&g_vp[((size_t)b * NN + m) * CC + o] = acc[op][px];
        }
    }
}

// ---------------------------------------------------------------------------
// Fused one-pass attention: per block 64 query rows x all 256 channels.
// Per 64-key tile: S = q.k (f32x2 over row pairs), exp (no max-sub; bounded),
// PV rank-1 update (f32x2 over channel pairs). Row sums kept as per-thread
// partials, reduced once at the end; epilogue: out = gamma*acc/sum + ef.
// ---------------------------------------------------------------------------
__global__ __launch_bounds__(256, 2) void attn_kernel(
    const float* __restrict__ ef, const float* __restrict__ gamma_p,
    float* __restrict__ out)
{
    extern __shared__ float sm[];
    float* qs = sm;                          // [d][m]   32x64
    float* ks = sm + 2048;                   // [d][n]   32xLDK
    float* Ps = sm + 2048 + 32 * LDK;        // [m][n]   64xLDPS
    float* vs = Ps + 64 * LDPS;              // [n][c]   64xLDVR (reused as obuf)
    __shared__ float gri[64];

    const int t  = threadIdx.x;
    const int m0 = blockIdx.x * 64;
    const int b  = blockIdx.y;
    const int bq = t >> 4, aa = t & 15;
    const int m4 = bq * 4, n4 = aa * 4;

    // load q tile [32 x 64]
#pragma unroll
    for (int i = 0; i < 2; i++) {
        int idx4 = i * 256 + t;
        int d = idx4 >> 4, mq = idx4 & 15;
        *(float4*)&qs[d * 64 + mq * 4] =
            *(const float4*)&g_q[((size_t)(b * DD + d)) * NN + m0 + mq * 4];
    }

    ull acc[4][8];
#pragma unroll
    for (int i = 0; i < 4; i++)
#pragma unroll
        for (int j = 0; j < 8; j++) acc[i][j] = 0ULL;
    float psum[4] = {0.f, 0.f, 0.f, 0.f};

    for (int n0 = 0; n0 < NN; n0 += 64) {
        // k tile [32 x 64]
#pragma unroll
        for (int i = 0; i < 2; i++) {
            int idx4 = i * 256 + t;
            int d = idx4 >> 4, nq = idx4 & 15;
            *(float4*)&ks[d * LDK + nq * 4] =
                *(const float4*)&g_k[((size_t)(b * DD + d)) * NN + n0 + nq * 4];
        }
        // v tile [64 x 256] (row-contiguous copy from interleaved g_vp)
#pragma unroll
        for (int i = 0; i < 16; i++) {
            int idx4 = i * 256 + t;
            int n = idx4 >> 6, q = idx4 & 63;
            *(float4*)&vs[n * LDVR + q * 4] =
                *(const float4*)&g_vp[((size_t)b * NN + n0 + n) * CC + q * 4];
        }
        __syncthreads();

        // S: 4m x 4n micro-tile, packed over row pairs
        {
            ull s2[2][4];
#pragma unroll
            for (int i = 0; i < 4; i++) { s2[0][i] = 0ULL; s2[1][i] = 0ULL; }
#pragma unroll
            for (int d = 0; d < DD; d++) {
                ull qa = *(const ull*)&qs[d * 64 + m4];
                ull qb = *(const ull*)&qs[d * 64 + m4 + 2];
#pragma unroll
                for (int i = 0; i < 4; i++) {
                    ull kd = dup2(ks[d * LDK + n4 + i]);
                    fma2(s2[0][i], qa, kd);
                    fma2(s2[1][i], qb, kd);
                }
            }
#pragma unroll
            for (int i = 0; i < 4; i++) {
                float2 va = unpk(s2[0][i]);
                float2 vb = unpk(s2[1][i]);
                Ps[(m4 + 0) * LDPS + n4 + i] = va.x;
                Ps[(m4 + 1) * LDPS + n4 + i] = va.y;
                Ps[(m4 + 2) * LDPS + n4 + i] = vb.x;
                Ps[(m4 + 3) * LDPS + n4 + i] = vb.y;
            }
        }
        __syncthreads();

        // exp (no max subtraction — scores bounded) + partial row sums
#pragma unroll
        for (int i = 0; i < 4; i++) {
            int m = i * 16 + bq;
            float4 v4 = *(float4*)&Ps[m * LDPS + aa * 4];
            v4.x = __expf(v4.x); v4.y = __expf(v4.y);
            v4.z = __expf(v4.z); v4.w = __expf(v4.w);
            *(float4*)&Ps[m * LDPS + aa * 4] = v4;
            psum[i] += (v4.x + v4.y) + (v4.z + v4.w);
        }
        __syncthreads();

        // PV: acc[mm][j] (f32x2 channel pair) += p * v, 2 keys per step
#pragma unroll 2
        for (int n = 0; n < 64; n += 2) {
            ull pa[4], pb[4];
#pragma unroll
            for (int mm = 0; mm < 4; mm++) {
                float2 p2 = *(const float2*)&Ps[(m4 + mm) * LDPS + n];
                pa[mm] = dup2(p2.x);
                pb[mm] = dup2(p2.y);
            }
#pragma unroll
            for (int j = 0; j < 8; j++) {
                ull va = *(const ull*)&vs[n * LDVR + (aa + 16 * j) * 2];
                ull vb = *(const ull*)&vs[(n + 1) * LDVR + (aa + 16 * j) * 2];
                fma2(acc[0][j], pa[0], va); fma2(acc[0][j], pb[0], vb);
                fma2(acc[1][j], pa[1], va); fma2(acc[1][j], pb[1], vb);
                fma2(acc[2][j], pa[2], va); fma2(acc[2][j], pb[2], vb);
                fma2(acc[3][j], pa[3], va); fma2(acc[3][j], pb[3], vb);
            }
        }
        __syncthreads();
    }

    // finalize row sums: butterfly over the 16 lanes sharing a row set
#pragma unroll
    for (int off = 1; off <= 8; off <<= 1)
#pragma unroll
        for (int i = 0; i < 4; i++)
            psum[i] += __shfl_xor_sync(0xffffffffu, psum[i], off);
    float gamma = gamma_p[0];
    if (aa == 0) {
#pragma unroll
        for (int i = 0; i < 4; i++)
            gri[i * 16 + bq] = gamma / psum[i];
    }

    // stage acc into obuf[c][m] (stride 65) for coalesced writes
#pragma unroll
    for (int j = 0; j < 8; j++) {
        int c = 2 * (aa + 16 * j);
#pragma unroll
        for (int mm = 0; mm < 4; mm++) {
            float2 o2 = unpk(acc[mm][j]);
            vs[c * 65 + m4 + mm]       = o2.x;
            vs[(c + 1) * 65 + m4 + mm] = o2.y;
        }
    }
    __syncthreads();

    // final: out = gamma*acc/sum + ef, coalesced float4 global I/O
#pragma unroll
    for (int i = 0; i < 16; i++) {
        int idx4 = i * 256 + t;
        int c = idx4 >> 4, mq = idx4 & 15;
        size_t gi = ((size_t)(b * CC + c)) * NN + m0 + mq * 4;
        float4 e4 = *(const float4*)&ef[gi];
        float4 o4;
        o4.x = vs[c * 65 + mq * 4 + 0] * gri[mq * 4 + 0] + e4.x;
        o4.y = vs[c * 65 + mq * 4 + 1] * gri[mq * 4 + 1] + e4.y;
        o4.z = vs[c * 65 + mq * 4 + 2] * gri[mq * 4 + 2] + e4.z;
        o4.w = vs[c * 65 + mq * 4 + 3] * gri[mq * 4 + 3] + e4.w;
        *(float4*)&out[gi] = o4;
    }
}

// ---------------------------------------------------------------------------
extern "C" void kernel_launch(void* const* d_in, const int* in_sizes, int n_in,
                              void* d_out, int out_size)
{
    const float* ef = (const float*)d_in[0];
    const float* sf = (const float*)d_in[1];
    const float* At = (const float*)d_in[2];
    const float* Qw = (const float*)d_in[3];
    const float* Qb = (const float*)d_in[4];
    const float* Kw = (const float*)d_in[5];
    const float* Kb = (const float*)d_in[6];
    const float* Vw = (const float*)d_in[7];
    const float* Vb = (const float*)d_in[8];
    const float* gm = (const float*)d_in[9];
    float* out = (float*)d_out;

    float *qp, *kp;
    cudaGetSymbolAddress((void**)&qp, g_q);
    cudaGetSymbolAddress((void**)&kp, g_k);

    cudaFuncSetAttribute(attn_kernel,
                         cudaFuncAttributeMaxDynamicSharedMemorySize, SMB);

    proj_kernel<<<dim3(NN / 128, 1, BN), 256>>>(ef, sf, CC, INCH, Qw, Qb, qp, DD);
    proj_kernel<<<dim3(NN / 128, 1, BN), 256>>>(At, At, CC, CC,  Kw, Kb, kp, DD);
    projV_kernel<<<dim3(NN / 128, CC / 32, BN), 256>>>(ef, sf, Vw, Vb);

    attn_kernel<<<dim3(NN / 64, BN), 256, SMB>>>(ef, gm, out);
}

// round 6
// speedup vs baseline: 2.7204x; 1.5472x over previous
#include <cuda_runtime.h>
#include <cuda_bf16.h>
#include <math.h>
#include <stdint.h>

#define BN   4
#define CC   256
#define NN   4096
#define DD   32
#define INCH 512

#define MT     64    // query rows per CTA
#define NT     64    // keys per tile
#define NTILES (NN / NT)

typedef unsigned long long ull;

// ---- dynamic smem byte offsets ----
#define OFF_QS   0                       // 32*64 fp32  = 8192
#define OFF_KS   8192                    // 32*68 fp32  = 8704
#define OFF_PS   16896                   // 64*72 bf16  = 9216
#define OFF_VS   26112                   // 256*72 bf16 = 36864 (ends 62976)
#define SMEM_B   66560                   // obuf overlay: 256*65*4 = 66560

__device__ float g_q[BN * DD * NN];
__device__ float g_k[BN * DD * NN];
__device__ __nv_bfloat16 g_vb[(size_t)BN * CC * NN];   // [b][c][n] channel-major

// ---- f32x2 helpers --------------------------------------------------------
__device__ __forceinline__ ull dup2(float x) {
    ull r; unsigned u = __float_as_uint(x);
    asm("mov.b64 %0, {%1, %1};" : "=l"(r) : "r"(u));
    return r;
}
__device__ __forceinline__ void fma2(ull& acc, ull a, ull b) {
    asm("fma.rn.f32x2 %0, %1, %2, %0;" : "+l"(acc) : "l"(a), "l"(b));
}
__device__ __forceinline__ void add2(ull& acc, ull b) {
    asm("add.rn.f32x2 %0, %1, %0;" : "+l"(acc) : "l"(b));
}
__device__ __forceinline__ float2 unpk(ull v) {
    unsigned lo, hi;
    asm("mov.b64 {%0, %1}, %2;" : "=r"(lo), "=r"(hi) : "l"(v));
    return make_float2(__uint_as_float(lo), __uint_as_float(hi));
}

// bf16 HMMA m16n8k16, fp32 accum
__device__ __forceinline__ void mma16816(float* c, const uint32_t* a,
                                         const uint32_t* b) {
    asm volatile(
        "mma.sync.aligned.m16n8k16.row.col.f32.bf16.bf16.f32 "
        "{%0,%1,%2,%3}, {%4,%5,%6,%7}, {%8,%9}, {%0,%1,%2,%3};"
        : "+f"(c[0]), "+f"(c[1]), "+f"(c[2]), "+f"(c[3])
        : "r"(a[0]), "r"(a[1]), "r"(a[2]), "r"(a[3]), "r"(b[0]), "r"(b[1]));
}

// ---------------------------------------------------------------------------
// 1x1 conv fp32 for Q and K
// ---------------------------------------------------------------------------
__global__ __launch_bounds__(256) void proj_kernel(
    const float* __restrict__ x1, const float* __restrict__ x2,
    int C1, int Ctot,
    const float* __restrict__ W, const float* __restrict__ bias,
    float* __restrict__ out, int O)
{
    __shared__ float Xs[16][128];
    __shared__ float Ws[16][32];
    const int m0 = blockIdx.x * 128;
    const int o0 = blockIdx.y * 32;
    const int b  = blockIdx.z;
    const int t  = threadIdx.x;
    const int tm = t & 31;
    const int to = t >> 5;

    float acc[4][4];
#pragma unroll
    for (int i = 0; i < 4; i++)
#pragma unroll
        for (int j = 0; j < 4; j++) acc[i][j] = 0.f;

    for (int c0 = 0; c0 < Ctot; c0 += 16) {
#pragma unroll
        for (int i = 0; i < 2; i++) {
            int idx = i * 256 + t;
            int r = idx >> 5, c4 = idx & 31;
            int c = c0 + r;
            const float* src = (c < C1)
                ? x1 + ((size_t)b * C1 + c) * NN
                : x2 + ((size_t)b * (Ctot - C1) + (c - C1)) * NN;
            *(float4*)&Xs[r][c4 * 4] = *(const float4*)&src[m0 + c4 * 4];
            Ws[r][c4] = W[(size_t)(o0 + c4) * Ctot + c0 + r];
        }
        __syncthreads();
#pragma unroll
        for (int kk = 0; kk < 16; kk++) {
            float4 xv = *(float4*)&Xs[kk][tm * 4];
            float4 wv = *(float4*)&Ws[kk][to * 4];
            acc[0][0] += wv.x * xv.x; acc[0][1] += wv.x * xv.y;
            acc[0][2] += wv.x * xv.z; acc[0][3] += wv.x * xv.w;
            acc[1][0] += wv.y * xv.x; acc[1][1] += wv.y * xv.y;
            acc[1][2] += wv.y * xv.z; acc[1][3] += wv.y * xv.w;
            acc[2][0] += wv.z * xv.x; acc[2][1] += wv.z * xv.y;
            acc[2][2] += wv.z * xv.z; acc[2][3] += wv.z * xv.w;
            acc[3][0] += wv.w * xv.x; acc[3][1] += wv.w * xv.y;
            acc[3][2] += wv.w * xv.z; acc[3][3] += wv.w * xv.w;
        }
        __syncthreads();
    }
#pragma unroll
    for (int oo = 0; oo < 4; oo++) {
        int o = o0 + to * 4 + oo;
        float bv = bias[o];
        float4 r4 = make_float4(acc[oo][0] + bv, acc[oo][1] + bv,
                                acc[oo][2] + bv, acc[oo][3] + bv);
        *(float4*)&out[((size_t)b * O + o) * NN + m0 + tm * 4] = r4;
    }
}

// ---------------------------------------------------------------------------
// V projection (f32x2 packed) -> bf16 channel-major g_vb[b][c][n]
// ---------------------------------------------------------------------------
__global__ __launch_bounds__(256) void projV_kernel(
    const float* __restrict__ x1, const float* __restrict__ x2,
    const float* __restrict__ W, const float* __restrict__ bias)
{
    __shared__ float Xs[16][128];
    __shared__ float Ws[16][32];
    const int m0 = blockIdx.x * 128;
    const int o0 = blockIdx.y * 32;
    const int b  = blockIdx.z;
    const int t  = threadIdx.x;
    const int tm = t & 31;
    const int to = t >> 5;

    ull acc[2][4];
#pragma unroll
    for (int i = 0; i < 2; i++)
#pragma unroll
        for (int j = 0; j < 4; j++) acc[i][j] = 0ULL;

    for (int c0 = 0; c0 < INCH; c0 += 16) {
#pragma unroll
        for (int i = 0; i < 2; i++) {
            int idx = i * 256 + t;
            int r = idx >> 5, c4 = idx & 31;
            int c = c0 + r;
            const float* src = (c < CC)
                ? x1 + ((size_t)b * CC + c) * NN
                : x2 + ((size_t)b * CC + (c - CC)) * NN;
            *(float4*)&Xs[r][c4 * 4] = *(const float4*)&src[m0 + c4 * 4];
            Ws[r][c4] = W[(size_t)(o0 + c4) * INCH + c0 + r];
        }
        __syncthreads();
#pragma unroll
        for (int kk = 0; kk < 16; kk++) {
            float4 xv = *(float4*)&Xs[kk][tm * 4];
            ull xd0 = dup2(xv.x), xd1 = dup2(xv.y);
            ull xd2 = dup2(xv.z), xd3 = dup2(xv.w);
            ull w0 = *(const ull*)&Ws[kk][to * 4];
            ull w1 = *(const ull*)&Ws[kk][to * 4 + 2];
            fma2(acc[0][0], w0, xd0); fma2(acc[0][1], w0, xd1);
            fma2(acc[0][2], w0, xd2); fma2(acc[0][3], w0, xd3);
            fma2(acc[1][0], w1, xd0); fma2(acc[1][1], w1, xd1);
            fma2(acc[1][2], w1, xd2); fma2(acc[1][3], w1, xd3);
        }
        __syncthreads();
    }
#pragma unroll
    for (int op = 0; op < 2; op++) {
        int o = o0 + to * 4 + 2 * op;
        ull b2 = *(const ull*)&bias[o];
        float vlo[4], vhi[4];
#pragma unroll
        for (int px = 0; px < 4; px++) {
            add2(acc[op][px], b2);
            float2 f = unpk(acc[op][px]);
            vlo[px] = f.x; vhi[px] = f.y;
        }
        __nv_bfloat162 a0 = __floats2bfloat162_rn(vlo[0], vlo[1]);
        __nv_bfloat162 a1 = __floats2bfloat162_rn(vlo[2], vlo[3]);
        __nv_bfloat162 b0 = __floats2bfloat162_rn(vhi[0], vhi[1]);
        __nv_bfloat162 b1 = __floats2bfloat162_rn(vhi[2], vhi[3]);
        size_t base = ((size_t)b * CC + o) * NN + m0 + tm * 4;
        *(uint2*)&g_vb[base]      = make_uint2(*(uint32_t*)&a0, *(uint32_t*)&a1);
        *(uint2*)&g_vb[base + NN] = make_uint2(*(uint32_t*)&b0, *(uint32_t*)&b1);
    }
}

// ---------------------------------------------------------------------------
// Attention: fp32 SIMT scores + exp -> bf16 P -> warp-level bf16 HMMA for PV.
// CTA = 64 query rows x 256 channels, 256 threads (8 warps), 64-key tiles.
// ---------------------------------------------------------------------------
__global__ __launch_bounds__(256, 2) void attn_kernel(
    const float* __restrict__ ef, const float* __restrict__ gamma_p,
    float* __restrict__ out)
{
    extern __shared__ __align__(16) char smem[];
    float* qs = (float*)(smem + OFF_QS);            // [d][m] 32x64
    float* ks = (float*)(smem + OFF_KS);            // [d][n] 32x68
    __nv_bfloat16* ps = (__nv_bfloat16*)(smem + OFF_PS);  // [m][k] 64x72
    __nv_bfloat16* vs = (__nv_bfloat16*)(smem + OFF_VS);  // [c][k] 256x72
    float* obuf = (float*)smem;                     // epilogue overlay [c][m] x65
    __shared__ float gri[64];

    const int t    = threadIdx.x;
    const int w    = t >> 5;
    const int lane = t & 31;
    const int b    = blockIdx.y;
    const int m0   = blockIdx.x * MT;

    // q tile once: [32 d][64 m]
#pragma unroll
    for (int i = 0; i < 2; i++) {
        int idx = i * 256 + t;
        int d = idx >> 4, mq = idx & 15;
        *(float4*)&qs[d * 64 + mq * 4] =
            *(const float4*)&g_q[((size_t)(b * DD + d)) * NN + m0 + mq * 4];
    }

    // S-phase thread map
    const int bq = t >> 4, aa = t & 15;
    const int m4 = bq * 4, n4 = aa * 4;
    // PV warp map: warp = (mg 0..1) x (ngr 0..3)
    const int mg = w >> 2, ngr = w & 3;
    const int mbase = mg * 32, nbase = ngr * 64;
    const int lr = lane >> 2, lc = lane & 3;

    float acc[2][8][4];
#pragma unroll
    for (int i = 0; i < 2; i++)
#pragma unroll
        for (int j = 0; j < 8; j++)
#pragma unroll
            for (int k = 0; k < 4; k++) acc[i][j][k] = 0.f;
    float psum[4] = {0.f, 0.f, 0.f, 0.f};

    for (int n0 = 0; n0 < NN; n0 += NT) {
        // K fp32 tile [32 d][64 n]
#pragma unroll
        for (int i = 0; i < 2; i++) {
            int idx = i * 256 + t;
            int d = idx >> 4, nq = idx & 15;
            *(float4*)&ks[d * 68 + nq * 4] =
                *(const float4*)&g_k[((size_t)(b * DD + d)) * NN + n0 + nq * 4];
        }
        // V bf16 tile [256 c][64 k]
#pragma unroll
        for (int it = 0; it < 8; it++) {
            int idx = it * 256 + t;
            int c = idx >> 3, q8 = idx & 7;
            *(uint4*)((char*)vs + c * 144 + q8 * 16) =
                *(const uint4*)&g_vb[((size_t)(b * CC + c)) * NN + n0 + q8 * 8];
        }
        __syncthreads();

        // S = q.k fp32 (4m x 4n per thread, f32x2 over row pairs)
        ull s2[2][4];
#pragma unroll
        for (int k = 0; k < 4; k++) { s2[0][k] = 0ULL; s2[1][k] = 0ULL; }
#pragma unroll
        for (int d = 0; d < DD; d++) {
            ull qa = *(const ull*)&qs[d * 64 + m4];
            ull qb = *(const ull*)&qs[d * 64 + m4 + 2];
            float4 kv = *(const float4*)&ks[d * 68 + n4];
            ull k0 = dup2(kv.x), k1 = dup2(kv.y), k2 = dup2(kv.z), k3 = dup2(kv.w);
            fma2(s2[0][0], qa, k0); fma2(s2[1][0], qb, k0);
            fma2(s2[0][1], qa, k1); fma2(s2[1][1], qb, k1);
            fma2(s2[0][2], qa, k2); fma2(s2[1][2], qb, k2);
            fma2(s2[0][3], qa, k3); fma2(s2[1][3], qb, k3);
        }
        // exp (bounded scores; no max-sub) + psum + bf16 P store
#pragma unroll
        for (int hf = 0; hf < 2; hf++) {
            float p0[4], p1[4];
#pragma unroll
            for (int k = 0; k < 4; k++) {
                float2 v = unpk(s2[hf][k]);
                p0[k] = __expf(v.x);
                p1[k] = __expf(v.y);
            }
            psum[2 * hf + 0] += (p0[0] + p0[1]) + (p0[2] + p0[3]);
            psum[2 * hf + 1] += (p1[0] + p1[1]) + (p1[2] + p1[3]);
            __nv_bfloat162 r0a = __floats2bfloat162_rn(p0[0], p0[1]);
            __nv_bfloat162 r0b = __floats2bfloat162_rn(p0[2], p0[3]);
            __nv_bfloat162 r1a = __floats2bfloat162_rn(p1[0], p1[1]);
            __nv_bfloat162 r1b = __floats2bfloat162_rn(p1[2], p1[3]);
            char* pr0 = (char*)ps + (m4 + 2 * hf) * 144 + aa * 8;
            char* pr1 = pr0 + 144;
            *(uint2*)pr0 = make_uint2(*(uint32_t*)&r0a, *(uint32_t*)&r0b);
            *(uint2*)pr1 = make_uint2(*(uint32_t*)&r1a, *(uint32_t*)&r1b);
        }
        __syncthreads();

        // PV: acc[M=64,N=256] += P[64,64] x V[256,64]^T via m16n8k16 bf16
#pragma unroll
        for (int kk = 0; kk < 4; kk++) {
            const int kb = kk * 16 + lc * 2;
            uint32_t afr[2][4];
#pragma unroll
            for (int i = 0; i < 2; i++) {
                const char* base = (const char*)ps + (mbase + i * 16 + lr) * 144 + kb * 2;
                afr[i][0] = *(const uint32_t*)(base);
                afr[i][1] = *(const uint32_t*)(base + 8 * 144);
                afr[i][2] = *(const uint32_t*)(base + 16);
                afr[i][3] = *(const uint32_t*)(base + 8 * 144 + 16);
            }
#pragma unroll
            for (int j = 0; j < 8; j++) {
                const char* vb = (const char*)vs + (nbase + j * 8 + lr) * 144 + kb * 2;
                uint32_t bfr[2];
                bfr[0] = *(const uint32_t*)(vb);
                bfr[1] = *(const uint32_t*)(vb + 16);
                mma16816(acc[0][j], afr[0], bfr);
                mma16816(acc[1][j], afr[1], bfr);
            }
        }
        __syncthreads();
    }

    // row-sum reduce (16 lanes per row-set) -> gri = gamma / psum
#pragma unroll
    for (int off = 1; off <= 8; off <<= 1)
#pragma unroll
        for (int k = 0; k < 4; k++)
            psum[k] += __shfl_xor_sync(0xffffffffu, psum[k], off);
    float gamma = gamma_p[0];
    if (aa == 0) {
#pragma unroll
        for (int k = 0; k < 4; k++) gri[m4 + k] = gamma / psum[k];
    }
    __syncthreads();   // all smem tiles dead; obuf overlay begins

    // stage acc into obuf[c][m] (stride 65)
#pragma unroll
    for (int i = 0; i < 2; i++) {
        int r = mbase + i * 16 + lr;
#pragma unroll
        for (int j = 0; j < 8; j++) {
            int c = nbase + j * 8 + lc * 2;
            obuf[c * 65 + r]           = acc[i][j][0];
            obuf[(c + 1) * 65 + r]     = acc[i][j][1];
            obuf[c * 65 + r + 8]       = acc[i][j][2];
            obuf[(c + 1) * 65 + r + 8] = acc[i][j][3];
        }
    }
    __syncthreads();

    // final: out = obuf * gri + ef, coalesced float4
#pragma unroll
    for (int i = 0; i < 16; i++) {
        int idx = i * 256 + t;
        int c = idx >> 4, mq = idx & 15;
        size_t gi = ((size_t)(b * CC + c)) * NN + m0 + mq * 4;
        float4 e4 = *(const float4*)&ef[gi];
        float4 o4;
        o4.x = obuf[c * 65 + mq * 4 + 0] * gri[mq * 4 + 0] + e4.x;
        o4.y = obuf[c * 65 + mq * 4 + 1] * gri[mq * 4 + 1] + e4.y;
        o4.z = obuf[c * 65 + mq * 4 + 2] * gri[mq * 4 + 2] + e4.z;
        o4.w = obuf[c * 65 + mq * 4 + 3] * gri[mq * 4 + 3] + e4.w;
        *(float4*)&out[gi] = o4;
    }
}

// ---------------------------------------------------------------------------
extern "C" void kernel_launch(void* const* d_in, const int* in_sizes, int n_in,
                              void* d_out, int out_size)
{
    const float* ef = (const float*)d_in[0];
    const float* sf = (const float*)d_in[1];
    const float* At = (const float*)d_in[2];
    const float* Qw = (const float*)d_in[3];
    const float* Qb = (const float*)d_in[4];
    const float* Kw = (const float*)d_in[5];
    const float* Kb = (const float*)d_in[6];
    const float* Vw = (const float*)d_in[7];
    const float* Vb = (const float*)d_in[8];
    const float* gm = (const float*)d_in[9];
    float* out = (float*)d_out;

    float *qp, *kp;
    cudaGetSymbolAddress((void**)&qp, g_q);
    cudaGetSymbolAddress((void**)&kp, g_k);

    cudaFuncSetAttribute(attn_kernel,
                         cudaFuncAttributeMaxDynamicSharedMemorySize, SMEM_B);

    proj_kernel<<<dim3(NN / 128, 1, BN), 256>>>(ef, sf, CC, INCH, Qw, Qb, qp, DD);
    proj_kernel<<<dim3(NN / 128, 1, BN), 256>>>(At, At, CC, CC,  Kw, Kb, kp, DD);
    projV_kernel<<<dim3(NN / 128, CC / 32, BN), 256>>>(ef, sf, Vw, Vb);

    attn_kernel<<<dim3(NN / MT, BN), 256, SMEM_B>>>(ef, gm, out);
}

// round 8
// speedup vs baseline: 6.4746x; 2.3800x over previous
#include <cuda_runtime.h>
#include <cuda_bf16.h>
#include <math.h>
#include <stdint.h>

#define BN   4
#define CC   256
#define NN   4096
#define DD   32
#define INCH 512

#define MT     64    // query rows per CTA (attn)
#define NT     64    // keys per tile

// attn dynamic smem (bytes)
#define OFF_KS   0                 // ks fp32 [32][72]  = 9216
#define OFF_VS   9216              // vs bf16 [256] rows of 144B = 36864
#define OFF_QS   OFF_VS            // qs fp32 [32][72] (pre-loop only, aliased)
#define SMEM_B   66560             // obuf overlay [256][65] fp32

__device__ float g_q[BN * DD * NN];
__device__ float g_k[BN * DD * NN];
__device__ __nv_bfloat16 g_vb[(size_t)BN * CC * NN];  // [b][c][n] channel-major
__device__ __nv_bfloat16 g_wvb[CC * INCH];            // bf16 V weights

// ---- mma / ldmatrix wrappers ---------------------------------------------
__device__ __forceinline__ void mma_tf32(float* d, const uint32_t* a,
                                         uint32_t b0, uint32_t b1) {
    asm volatile(
        "mma.sync.aligned.m16n8k8.row.col.f32.tf32.tf32.f32 "
        "{%0,%1,%2,%3}, {%4,%5,%6,%7}, {%8,%9}, {%0,%1,%2,%3};"
        : "+f"(d[0]), "+f"(d[1]), "+f"(d[2]), "+f"(d[3])
        : "r"(a[0]), "r"(a[1]), "r"(a[2]), "r"(a[3]), "r"(b0), "r"(b1));
}
__device__ __forceinline__ void mma_bf16(float* d, const uint32_t* a,
                                         uint32_t b0, uint32_t b1) {
    asm volatile(
        "mma.sync.aligned.m16n8k16.row.col.f32.bf16.bf16.f32 "
        "{%0,%1,%2,%3}, {%4,%5,%6,%7}, {%8,%9}, {%0,%1,%2,%3};"
        : "+f"(d[0]), "+f"(d[1]), "+f"(d[2]), "+f"(d[3])
        : "r"(a[0]), "r"(a[1]), "r"(a[2]), "r"(a[3]), "r"(b0), "r"(b1));
}
__device__ __forceinline__ void ldsm_x4(uint32_t& r0, uint32_t& r1,
                                        uint32_t& r2, uint32_t& r3,
                                        uint32_t addr) {
    asm volatile("ldmatrix.sync.aligned.m8n8.x4.shared.b16 {%0,%1,%2,%3}, [%4];"
                 : "=r"(r0), "=r"(r1), "=r"(r2), "=r"(r3) : "r"(addr));
}
__device__ __forceinline__ void ldsm_x4t(uint32_t& r0, uint32_t& r1,
                                         uint32_t& r2, uint32_t& r3,
                                         uint32_t addr) {
    asm volatile("ldmatrix.sync.aligned.m8n8.x4.trans.shared.b16 {%0,%1,%2,%3}, [%4];"
                 : "=r"(r0), "=r"(r1), "=r"(r2), "=r"(r3) : "r"(addr));
}
__device__ __forceinline__ uint32_t smem_u32(const void* p) {
    uint32_t a;
    asm("{ .reg .u64 t; cvta.to.shared.u64 t, %1; cvt.u32.u64 %0, t; }"
        : "=r"(a) : "l"(p));
    return a;
}
__device__ __forceinline__ uint32_t pkbf(float a, float b) {
    __nv_bfloat162 h = __floats2bfloat162_rn(a, b);
    return *(uint32_t*)&h;
}

// ---------------------------------------------------------------------------
// fp32 1x1 conv for Q and K (unchanged)
// ---------------------------------------------------------------------------
__global__ __launch_bounds__(256) void proj_kernel(
    const float* __restrict__ x1, const float* __restrict__ x2,
    int C1, int Ctot,
    const float* __restrict__ W, const float* __restrict__ bias,
    float* __restrict__ out, int O)
{
    __shared__ float Xs[16][128];
    __shared__ float Ws[16][32];
    const int m0 = blockIdx.x * 128;
    const int o0 = blockIdx.y * 32;
    const int b  = blockIdx.z;
    const int t  = threadIdx.x;
    const int tm = t & 31;
    const int to = t >> 5;

    float acc[4][4];
#pragma unroll
    for (int i = 0; i < 4; i++)
#pragma unroll
        for (int j = 0; j < 4; j++) acc[i][j] = 0.f;

    for (int c0 = 0; c0 < Ctot; c0 += 16) {
#pragma unroll
        for (int i = 0; i < 2; i++) {
            int idx = i * 256 + t;
            int r = idx >> 5, c4 = idx & 31;
            int c = c0 + r;
            const float* src = (c < C1)
                ? x1 + ((size_t)b * C1 + c) * NN
                : x2 + ((size_t)b * (Ctot - C1) + (c - C1)) * NN;
            *(float4*)&Xs[r][c4 * 4] = *(const float4*)&src[m0 + c4 * 4];
            Ws[r][c4] = W[(size_t)(o0 + c4) * Ctot + c0 + r];
        }
        __syncthreads();
#pragma unroll
        for (int kk = 0; kk < 16; kk++) {
            float4 xv = *(float4*)&Xs[kk][tm * 4];
            float4 wv = *(float4*)&Ws[kk][to * 4];
            acc[0][0] += wv.x * xv.x; acc[0][1] += wv.x * xv.y;
            acc[0][2] += wv.x * xv.z; acc[0][3] += wv.x * xv.w;
            acc[1][0] += wv.y * xv.x; acc[1][1] += wv.y * xv.y;
            acc[1][2] += wv.y * xv.z; acc[1][3] += wv.y * xv.w;
            acc[2][0] += wv.z * xv.x; acc[2][1] += wv.z * xv.y;
            acc[2][2] += wv.z * xv.z; acc[2][3] += wv.z * xv.w;
            acc[3][0] += wv.w * xv.x; acc[3][1] += wv.w * xv.y;
            acc[3][2] += wv.w * xv.z; acc[3][3] += wv.w * xv.w;
        }
        __syncthreads();
    }
#pragma unroll
    for (int oo = 0; oo < 4; oo++) {
        int o = o0 + to * 4 + oo;
        float bv = bias[o];
        float4 r4 = make_float4(acc[oo][0] + bv, acc[oo][1] + bv,
                                acc[oo][2] + bv, acc[oo][3] + bv);
        *(float4*)&out[((size_t)b * O + o) * NN + m0 + tm * 4] = r4;
    }
}

// ---------------------------------------------------------------------------
// convert V weights fp32 -> bf16 (once)
// ---------------------------------------------------------------------------
__global__ void wconv_kernel(const float* __restrict__ W) {
    int i = (blockIdx.x * 256 + threadIdx.x) * 4;
    float4 v = *(const float4*)&W[i];
    uint2 o = make_uint2(pkbf(v.x, v.y), pkbf(v.z, v.w));
    *(uint2*)&g_wvb[i] = o;
}

// ---------------------------------------------------------------------------
// V projection via bf16 HMMA: g_vb[b][c][n] (+bias), x converted on the fly.
// CTA: 64 out-ch x 128 px; 8 warps = 4 o-tiles x 2 m-halves.
// ---------------------------------------------------------------------------
__global__ __launch_bounds__(256) void projV_kernel(
    const float* __restrict__ x1, const float* __restrict__ x2,
    const float* __restrict__ bias)
{
    __shared__ __align__(16) char xs[16 * 272];   // [k16][m128] bf16, 272B rows
    const int m0 = blockIdx.x * 128;
    const int o0 = blockIdx.y * 64;
    const int b  = blockIdx.z;
    const int t  = threadIdx.x;
    const int w  = t >> 5, lane = t & 31;
    const int lr = lane >> 2, lc = lane & 3;
    const int wo = w >> 1, wmh = w & 1;
    const uint32_t xsb = smem_u32(xs);

    float acc[8][4];
#pragma unroll
    for (int i = 0; i < 8; i++)
#pragma unroll
        for (int j = 0; j < 4; j++) acc[i][j] = 0.f;

    const int fk = t >> 4, fm = t & 15;   // fill map: k row, m segment(8)

    for (int c0 = 0; c0 < INCH; c0 += 16) {
        // fill xs[k][m] bf16 from fp32 x
        {
            int ci = c0 + fk;
            const float* src = (ci < CC)
                ? x1 + ((size_t)b * CC + ci) * NN
                : x2 + ((size_t)b * CC + (ci - CC)) * NN;
            float4 v0 = *(const float4*)&src[m0 + fm * 8];
            float4 v1 = *(const float4*)&src[m0 + fm * 8 + 4];
            uint4 o = make_uint4(pkbf(v0.x, v0.y), pkbf(v0.z, v0.w),
                                 pkbf(v1.x, v1.y), pkbf(v1.z, v1.w));
            *(uint4*)(xs + fk * 272 + fm * 16) = o;
        }
        __syncthreads();
        // A-frags (W) straight from global bf16 (L1/L2 resident)
        uint32_t a[4];
        {
            const __nv_bfloat16* wr = g_wvb + (size_t)(o0 + wo * 16 + lr) * INCH + c0;
            a[0] = *(const uint32_t*)(wr + 2 * lc);
            a[1] = *(const uint32_t*)(wr + 8 * INCH + 2 * lc);
            a[2] = *(const uint32_t*)(wr + 2 * lc + 8);
            a[3] = *(const uint32_t*)(wr + 8 * INCH + 2 * lc + 8);
        }
        // B-frags via ldmatrix.trans; 2 n8-blocks per x4
        const int mloc = wmh * 64;
#pragma unroll
        for (int nt = 0; nt < 8; nt += 2) {
            uint32_t r0, r1, r2, r3;
            // lanes 0-7: (k0-7, m nt); 8-15: (k8-15, m nt); 16-23: (k0-7, nt+1); 24-31: (k8-15, nt+1)
            uint32_t addr = xsb + ((lane & 7) + ((lane >> 3) & 1) * 8) * 272
                          + (mloc + (nt + (lane >> 4)) * 8) * 2;
            ldsm_x4t(r0, r1, r2, r3, addr);
            mma_bf16(acc[nt],     a, r0, r1);
            mma_bf16(acc[nt + 1], a, r2, r3);
        }
        __syncthreads();
    }
    // epilogue: add bias, round to bf16, store channel-major
    const int o = o0 + wo * 16 + lr;
    float b0 = bias[o], b1 = bias[o + 8];
#pragma unroll
    for (int nt = 0; nt < 8; nt++) {
        int m = m0 + wmh * 64 + nt * 8 + 2 * lc;
        size_t gi = ((size_t)(b * CC + o)) * NN + m;
        *(uint32_t*)&g_vb[gi] = pkbf(acc[nt][0] + b0, acc[nt][1] + b0);
        *(uint32_t*)&g_vb[gi + 8 * NN] = pkbf(acc[nt][2] + b1, acc[nt][3] + b1);
    }
}

// ---------------------------------------------------------------------------
// Attention (FA2-style): tf32 HMMA scores (q resident), exp in registers,
// P register-chained into bf16 HMMA PV with V via ldmatrix.
// CTA: 64 rows x 256 ch; 8 warps = 4 m-tiles x 2 channel-halves.
// ---------------------------------------------------------------------------
__global__ __launch_bounds__(256, 2) void attn_kernel(
    const float* __restrict__ ef, const float* __restrict__ gamma_p,
    float* __restrict__ out)
{
    extern __shared__ __align__(16) char smem[];
    float* ks = (float*)(smem + OFF_KS);   // [k32][n64] stride 72
    float* qs = (float*)(smem + OFF_QS);   // [k32][m64] stride 72 (pre-loop)
    char*  vs = smem + OFF_VS;             // [c256] rows of 144B (k64 bf16)
    float* obuf = (float*)smem;            // epilogue overlay [c][m] stride 65
    __shared__ float gri[64];

    const int t = threadIdx.x;
    const int w = t >> 5, lane = t & 31;
    const int lr = lane >> 2, lc = lane & 3;
    const int wm = w >> 1, wn = w & 1;
    const int b  = blockIdx.y;
    const int m0 = blockIdx.x * MT;
    const uint32_t vsb = smem_u32(vs);

    // stage q [32][64] then extract resident tf32 A-frags
#pragma unroll
    for (int i = 0; i < 2; i++) {
        int idx = i * 256 + t;
        int d = idx >> 4, mq = idx & 15;
        *(float4*)&qs[d * 72 + mq * 4] =
            *(const float4*)&g_q[((size_t)(b * DD + d)) * NN + m0 + mq * 4];
    }
    __syncthreads();
    uint32_t qf[4][4];
    {
        const int m = wm * 16 + lr;
#pragma unroll
        for (int k4 = 0; k4 < 4; k4++) {
            qf[k4][0] = __float_as_uint(qs[(k4 * 8 + lc) * 72 + m]);
            qf[k4][1] = __float_as_uint(qs[(k4 * 8 + lc) * 72 + m + 8]);
            qf[k4][2] = __float_as_uint(qs[(k4 * 8 + lc + 4) * 72 + m]);
            qf[k4][3] = __float_as_uint(qs[(k4 * 8 + lc + 4) * 72 + m + 8]);
        }
    }
    __syncthreads();

    float acc[16][4];
#pragma unroll
    for (int i = 0; i < 16; i++)
#pragma unroll
        for (int j = 0; j < 4; j++) acc[i][j] = 0.f;
    float psum_lo = 0.f, psum_hi = 0.f;
    const int nbase = wn * 128;

    for (int n0 = 0; n0 < NN; n0 += NT) {
        // ---- fill ks [32][64] fp32, vs [256][64] bf16
#pragma unroll
        for (int i = 0; i < 2; i++) {
            int idx = i * 256 + t;
            int d = idx >> 4, nq = idx & 15;
            *(float4*)&ks[d * 72 + nq * 4] =
                *(const float4*)&g_k[((size_t)(b * DD + d)) * NN + n0 + nq * 4];
        }
#pragma unroll
        for (int it = 0; it < 8; it++) {
            int idx = it * 256 + t;
            int c = idx >> 3, seg = idx & 7;
            *(uint4*)(vs + c * 144 + seg * 16) =
                *(const uint4*)&g_vb[((size_t)(b * CC + c)) * NN + n0 + seg * 8];
        }
        __syncthreads();

        // ---- S + exp + PV, in two key-halves of 32
        uint32_t pv_a[4][4];
#pragma unroll
        for (int h = 0; h < 2; h++) {
            float sacc[4][4];
#pragma unroll
            for (int l = 0; l < 4; l++)
#pragma unroll
                for (int j = 0; j < 4; j++) sacc[l][j] = 0.f;
#pragma unroll
            for (int k4 = 0; k4 < 4; k4++) {
                const int kr = k4 * 8;
#pragma unroll
                for (int l = 0; l < 4; l++) {
                    int n = (4 * h + l) * 8 + lr;
                    uint32_t b0 = __float_as_uint(ks[(kr + lc) * 72 + n]);
                    uint32_t b1 = __float_as_uint(ks[(kr + lc + 4) * 72 + n]);
                    mma_tf32(sacc[l], qf[k4], b0, b1);
                }
            }
            // exp (bounded, no max-sub), psum, pack to PV A-frags
#pragma unroll
            for (int p = 0; p < 2; p++) {          // p: kt within half
                float e00 = __expf(sacc[2 * p][0]), e01 = __expf(sacc[2 * p][1]);
                float e02 = __expf(sacc[2 * p][2]), e03 = __expf(sacc[2 * p][3]);
                float e10 = __expf(sacc[2 * p + 1][0]), e11 = __expf(sacc[2 * p + 1][1]);
                float e12 = __expf(sacc[2 * p + 1][2]), e13 = __expf(sacc[2 * p + 1][3]);
                psum_lo += (e00 + e01) + (e10 + e11);
                psum_hi += (e02 + e03) + (e12 + e13);
                pv_a[2 * h + p][0] = pkbf(e00, e01);
                pv_a[2 * h + p][1] = pkbf(e02, e03);
                pv_a[2 * h + p][2] = pkbf(e10, e11);
                pv_a[2 * h + p][3] = pkbf(e12, e13);
            }
        }

        // ---- PV: acc[m16, c128] += P[m16,k64] x V[c128,k64]^T
#pragma unroll
        for (int ntc = 0; ntc < 16; ntc++) {
            uint32_t base = vsb + (nbase + ntc * 8 + (lane & 7)) * 144
                          + ((lane >> 3) * 16);
            uint32_t v0, v1, v2, v3;
            ldsm_x4(v0, v1, v2, v3, base);
            mma_bf16(acc[ntc], pv_a[0], v0, v1);
            mma_bf16(acc[ntc], pv_a[1], v2, v3);
            ldsm_x4(v0, v1, v2, v3, base + 64);
            mma_bf16(acc[ntc], pv_a[2], v0, v1);
            mma_bf16(acc[ntc], pv_a[3], v2, v3);
        }
        __syncthreads();
    }

    // ---- row-sum reduce over the 4 lanes sharing a row; wn==0 writes gri
    psum_lo += __shfl_xor_sync(0xffffffffu, psum_lo, 1);
    psum_lo += __shfl_xor_sync(0xffffffffu, psum_lo, 2);
    psum_hi += __shfl_xor_sync(0xffffffffu, psum_hi, 1);
    psum_hi += __shfl_xor_sync(0xffffffffu, psum_hi, 2);
    float gamma = gamma_p[0];
    if (wn == 0 && lc == 0) {
        gri[wm * 16 + lr]     = gamma / psum_lo;
        gri[wm * 16 + lr + 8] = gamma / psum_hi;
    }
    __syncthreads();

    // ---- stage acc into obuf[c][m]
#pragma unroll
    for (int ntc = 0; ntc < 16; ntc++) {
        int c = nbase + ntc * 8 + 2 * lc;
        int m = wm * 16 + lr;
        obuf[c * 65 + m]           = acc[ntc][0];
        obuf[(c + 1) * 65 + m]     = acc[ntc][1];
        obuf[c * 65 + m + 8]       = acc[ntc][2];
        obuf[(c + 1) * 65 + m + 8] = acc[ntc][3];
    }
    __syncthreads();

    // ---- final: out = obuf * gri + ef, coalesced float4
#pragma unroll
    for (int i = 0; i < 16; i++) {
        int idx = i * 256 + t;
        int c = idx >> 4, mq = idx & 15;
        size_t gi = ((size_t)(b * CC + c)) * NN + m0 + mq * 4;
        float4 e4 = *(const float4*)&ef[gi];
        float4 o4;
        o4.x = obuf[c * 65 + mq * 4 + 0] * gri[mq * 4 + 0] + e4.x;
        o4.y = obuf[c * 65 + mq * 4 + 1] * gri[mq * 4 + 1] + e4.y;
        o4.z = obuf[c * 65 + mq * 4 + 2] * gri[mq * 4 + 2] + e4.z;
        o4.w = obuf[c * 65 + mq * 4 + 3] * gri[mq * 4 + 3] + e4.w;
        *(float4*)&out[gi] = o4;
    }
}

// ---------------------------------------------------------------------------
extern "C" void kernel_launch(void* const* d_in, const int* in_sizes, int n_in,
                              void* d_out, int out_size)
{
    const float* ef = (const float*)d_in[0];
    const float* sf = (const float*)d_in[1];
    const float* At = (const float*)d_in[2];
    const float* Qw = (const float*)d_in[3];
    const float* Qb = (const float*)d_in[4];
    const float* Kw = (const float*)d_in[5];
    const float* Kb = (const float*)d_in[6];
    const float* Vw = (const float*)d_in[7];
    const float* Vb = (const float*)d_in[8];
    const float* gm = (const float*)d_in[9];
    float* out = (float*)d_out;

    float *qp, *kp;
    cudaGetSymbolAddress((void**)&qp, g_q);
    cudaGetSymbolAddress((void**)&kp, g_k);

    cudaFuncSetAttribute(attn_kernel,
                         cudaFuncAttributeMaxDynamicSharedMemorySize, SMEM_B);

    wconv_kernel<<<CC * INCH / 1024, 256>>>(Vw);
    proj_kernel<<<dim3(NN / 128, 1, BN), 256>>>(ef, sf, CC, INCH, Qw, Qb, qp, DD);
    proj_kernel<<<dim3(NN / 128, 1, BN), 256>>>(At, At, CC, CC,  Kw, Kb, kp, DD);
    projV_kernel<<<dim3(NN / 128, CC / 64, BN), 256>>>(ef, sf, Vb);

    attn_kernel<<<dim3(NN / MT, BN), 256, SMEM_B>>>(ef, gm, out);
}

// round 11
// speedup vs baseline: 7.6400x; 1.1800x over previous
#include <cuda_runtime.h>
#include <cuda_bf16.h>
#include <math.h>
#include <stdint.h>

#define BN   4
#define CC   256
#define NN   4096
#define DD   32
#define INCH 512

#define MT     128   // query rows per CTA (attn)
#define NT     64    // keys per tile

// attn dynamic smem (bytes)
#define OFF_KS   0                 // ks fp32 [32][72]  = 9216
#define OFF_VS   9216              // vs bf16 [256] rows of 144B = 36864
#define OFF_QS   OFF_VS            // qs fp32 [32][132] (pre-loop, aliased)
#define SMEM_ATT 135168            // obuf overlay [256][132] fp32

__device__ float g_q[BN * DD * NN];
__device__ float g_k[BN * DD * NN];
__device__ __nv_bfloat16 g_vb[(size_t)BN * CC * NN];  // [b][c][n] channel-major
__device__ __nv_bfloat16 g_wvb[CC * INCH];            // bf16 V weights

// ---- mma / ldmatrix wrappers ---------------------------------------------
__device__ __forceinline__ void mma_tf32(float* d, const uint32_t* a,
                                         uint32_t b0, uint32_t b1) {
    asm volatile(
        "mma.sync.aligned.m16n8k8.row.col.f32.tf32.tf32.f32 "
        "{%0,%1,%2,%3}, {%4,%5,%6,%7}, {%8,%9}, {%0,%1,%2,%3};"
        : "+f"(d[0]), "+f"(d[1]), "+f"(d[2]), "+f"(d[3])
        : "r"(a[0]), "r"(a[1]), "r"(a[2]), "r"(a[3]), "r"(b0), "r"(b1));
}
__device__ __forceinline__ void mma_bf16(float* d, const uint32_t* a,
                                         uint32_t b0, uint32_t b1) {
    asm volatile(
        "mma.sync.aligned.m16n8k16.row.col.f32.bf16.bf16.f32 "
        "{%0,%1,%2,%3}, {%4,%5,%6,%7}, {%8,%9}, {%0,%1,%2,%3};"
        : "+f"(d[0]), "+f"(d[1]), "+f"(d[2]), "+f"(d[3])
        : "r"(a[0]), "r"(a[1]), "r"(a[2]), "r"(a[3]), "r"(b0), "r"(b1));
}
__device__ __forceinline__ void ldsm_x4(uint32_t& r0, uint32_t& r1,
                                        uint32_t& r2, uint32_t& r3,
                                        uint32_t addr) {
    asm volatile("ldmatrix.sync.aligned.m8n8.x4.shared.b16 {%0,%1,%2,%3}, [%4];"
                 : "=r"(r0), "=r"(r1), "=r"(r2), "=r"(r3) : "r"(addr));
}
__device__ __forceinline__ void ldsm_x4t(uint32_t& r0, uint32_t& r1,
                                         uint32_t& r2, uint32_t& r3,
                                         uint32_t addr) {
    asm volatile("ldmatrix.sync.aligned.m8n8.x4.trans.shared.b16 {%0,%1,%2,%3}, [%4];"
                 : "=r"(r0), "=r"(r1), "=r"(r2), "=r"(r3) : "r"(addr));
}
__device__ __forceinline__ uint32_t smem_u32(const void* p) {
    uint32_t a;
    asm("{ .reg .u64 t; cvta.to.shared.u64 t, %1; cvt.u32.u64 %0, t; }"
        : "=r"(a) : "l"(p));
    return a;
}
__device__ __forceinline__ uint32_t pkbf(float a, float b) {
    __nv_bfloat162 h = __floats2bfloat162_rn(a, b);
    return *(uint32_t*)&h;
}

// ---------------------------------------------------------------------------
// Q/K projection via tf32 HMMA. O=32 out-ch, CTA = 128 px.
// 8 warps = 2 o-tiles (m16) x 4 px-groups (n32).
// ---------------------------------------------------------------------------
__global__ __launch_bounds__(256) void projQK_kernel(
    const float* __restrict__ x1, const float* __restrict__ x2,
    int C1, int Ctot,
    const float* __restrict__ W, const float* __restrict__ bias,
    float* __restrict__ out)
{
    __shared__ __align__(16) float xs[16 * 136];   // [k16][m128] stride 136
    const int m0 = blockIdx.x * 128;
    const int b  = blockIdx.z;
    const int t  = threadIdx.x;
    const int w  = t >> 5, lane = t & 31;
    const int lr = lane >> 2, lc = lane & 3;
    const int wo = w >> 2, wn = w & 3;

    float acc[4][4];
#pragma unroll
    for (int i = 0; i < 4; i++)
#pragma unroll
        for (int j = 0; j < 4; j++) acc[i][j] = 0.f;

    for (int c0 = 0; c0 < Ctot; c0 += 16) {
#pragma unroll
        for (int i = 0; i < 2; i++) {
            int idx = i * 256 + t;
            int r = idx >> 5, c4 = idx & 31;
            int c = c0 + r;
            const float* src = (c < C1)
                ? x1 + ((size_t)b * C1 + c) * NN
                : x2 + ((size_t)b * (Ctot - C1) + (c - C1)) * NN;
            *(float4*)&xs[r * 136 + c4 * 4] = *(const float4*)&src[m0 + c4 * 4];
        }
        __syncthreads();
#pragma unroll
        for (int k8 = 0; k8 < 2; k8++) {
            const float* wr = W + (size_t)(wo * 16 + lr) * Ctot + c0 + k8 * 8;
            uint32_t a[4];
            a[0] = __float_as_uint(wr[lc]);
            a[1] = __float_as_uint(wr[8 * Ctot + lc]);
            a[2] = __float_as_uint(wr[lc + 4]);
            a[3] = __float_as_uint(wr[8 * Ctot + lc + 4]);
#pragma unroll
            for (int nt = 0; nt < 4; nt++) {
                int n = wn * 32 + nt * 8 + lr;
                uint32_t b0 = __float_as_uint(xs[(k8 * 8 + lc) * 136 + n]);
                uint32_t b1 = __float_as_uint(xs[(k8 * 8 + lc + 4) * 136 + n]);
                mma_tf32(acc[nt], a, b0, b1);
            }
        }
        __syncthreads();
    }
    const int o = wo * 16 + lr;
    float bo0 = bias[o], bo1 = bias[o + 8];
#pragma unroll
    for (int nt = 0; nt < 4; nt++) {
        int m = m0 + wn * 32 + nt * 8 + 2 * lc;
        *(float2*)&out[((size_t)(b * 32 + o)) * NN + m] =
            make_float2(acc[nt][0] + bo0, acc[nt][1] + bo0);
        *(float2*)&out[((size_t)(b * 32 + o + 8)) * NN + m] =
            make_float2(acc[nt][2] + bo1, acc[nt][3] + bo1);
    }
}

// ---------------------------------------------------------------------------
// convert V weights fp32 -> bf16 (once)
// ---------------------------------------------------------------------------
__global__ void wconv_kernel(const float* __restrict__ W) {
    int i = (blockIdx.x * 256 + threadIdx.x) * 4;
    float4 v = *(const float4*)&W[i];
    uint2 o = make_uint2(pkbf(v.x, v.y), pkbf(v.z, v.w));
    *(uint2*)&g_wvb[i] = o;
}

// ---------------------------------------------------------------------------
// V projection via bf16 HMMA -> g_vb[b][c][n] (+bias)
// ---------------------------------------------------------------------------
__global__ __launch_bounds__(256) void projV_kernel(
    const float* __restrict__ x1, const float* __restrict__ x2,
    const float* __restrict__ bias)
{
    __shared__ __align__(16) char xs[16 * 272];   // [k16][m128] bf16, 272B rows
    const int m0 = blockIdx.x * 128;
    const int o0 = blockIdx.y * 64;
    const int b  = blockIdx.z;
    const int t  = threadIdx.x;
    const int w  = t >> 5, lane = t & 31;
    const int lr = lane >> 2, lc = lane & 3;
    const int wo = w >> 1, wmh = w & 1;
    const uint32_t xsb = smem_u32(xs);

    float acc[8][4];
#pragma unroll
    for (int i = 0; i < 8; i++)
#pragma unroll
        for (int j = 0; j < 4; j++) acc[i][j] = 0.f;

    const int fk = t >> 4, fm = t & 15;

    for (int c0 = 0; c0 < INCH; c0 += 16) {
        {
            int ci = c0 + fk;
            const float* src = (ci < CC)
                ? x1 + ((size_t)b * CC + ci) * NN
                : x2 + ((size_t)b * CC + (ci - CC)) * NN;
            float4 v0 = *(const float4*)&src[m0 + fm * 8];
            float4 v1 = *(const float4*)&src[m0 + fm * 8 + 4];
            uint4 o = make_uint4(pkbf(v0.x, v0.y), pkbf(v0.z, v0.w),
                                 pkbf(v1.x, v1.y), pkbf(v1.z, v1.w));
            *(uint4*)(xs + fk * 272 + fm * 16) = o;
        }
        __syncthreads();
        uint32_t a[4];
        {
            const __nv_bfloat16* wr = g_wvb + (size_t)(o0 + wo * 16 + lr) * INCH + c0;
            a[0] = *(const uint32_t*)(wr + 2 * lc);
            a[1] = *(const uint32_t*)(wr + 8 * INCH + 2 * lc);
            a[2] = *(const uint32_t*)(wr + 2 * lc + 8);
            a[3] = *(const uint32_t*)(wr + 8 * INCH + 2 * lc + 8);
        }
        const int mloc = wmh * 64;
#pragma unroll
        for (int nt = 0; nt < 8; nt += 2) {
            uint32_t r0, r1, r2, r3;
            uint32_t addr = xsb + ((lane & 7) + ((lane >> 3) & 1) * 8) * 272
                          + (mloc + (nt + (lane >> 4)) * 8) * 2;
            ldsm_x4t(r0, r1, r2, r3, addr);
            mma_bf16(acc[nt],     a, r0, r1);
            mma_bf16(acc[nt + 1], a, r2, r3);
        }
        __syncthreads();
    }
    const int o = o0 + wo * 16 + lr;
    float b0 = bias[o], b1 = bias[o + 8];
#pragma unroll
    for (int nt = 0; nt < 8; nt++) {
        int m = m0 + wmh * 64 + nt * 8 + 2 * lc;
        size_t gi = ((size_t)(b * CC + o)) * NN + m;
        *(uint32_t*)&g_vb[gi] = pkbf(acc[nt][0] + b0, acc[nt][1] + b0);
        *(uint32_t*)&g_vb[gi + 8 * NN] = pkbf(acc[nt][2] + b1, acc[nt][3] + b1);
    }
}

// ---------------------------------------------------------------------------
// Attention FA2: tf32 S (each warp owns m16 x ALL 256 channels — no S dup),
// exp in regs, P register-chained into bf16 HMMA PV.
// CTA = 128 rows, 8 warps, 256 threads, 1 CTA/SM.
// ---------------------------------------------------------------------------
__global__ __launch_bounds__(256, 1) void attn_kernel(
    const float* __restrict__ ef, const float* __restrict__ gamma_p,
    float* __restrict__ out)
{
    extern __shared__ __align__(16) char smem[];
    float* ks = (float*)(smem + OFF_KS);   // [k32][n64] stride 72
    float* qs = (float*)(smem + OFF_QS);   // [k32][m128] stride 132 (pre-loop)
    char*  vs = smem + OFF_VS;             // [c256] rows of 144B
    float* obuf = (float*)smem;            // epilogue overlay [c][m] stride 132
    __shared__ float gri[128];

    const int t = threadIdx.x;
    const int w = t >> 5, lane = t & 31;
    const int lr = lane >> 2, lc = lane & 3;
    const int b  = blockIdx.y;
    const int m0 = blockIdx.x * MT;
    const uint32_t vsb = smem_u32(vs);

    // stage q [32][128], extract resident tf32 A-frags
#pragma unroll
    for (int i = 0; i < 4; i++) {
        int idx = i * 256 + t;
        int d = idx >> 5, mq = idx & 31;
        *(float4*)&qs[d * 132 + mq * 4] =
            *(const float4*)&g_q[((size_t)(b * DD + d)) * NN + m0 + mq * 4];
    }
    __syncthreads();
    uint32_t qf[4][4];
    {
        const int m = w * 16 + lr;
#pragma unroll
        for (int k4 = 0; k4 < 4; k4++) {
            qf[k4][0] = __float_as_uint(qs[(k4 * 8 + lc) * 132 + m]);
            qf[k4][1] = __float_as_uint(qs[(k4 * 8 + lc) * 132 + m + 8]);
            qf[k4][2] = __float_as_uint(qs[(k4 * 8 + lc + 4) * 132 + m]);
            qf[k4][3] = __float_as_uint(qs[(k4 * 8 + lc + 4) * 132 + m + 8]);
        }
    }
    __syncthreads();

    float acc[32][4];
#pragma unroll
    for (int i = 0; i < 32; i++)
#pragma unroll
        for (int j = 0; j < 4; j++) acc[i][j] = 0.f;
    float psum_lo = 0.f, psum_hi = 0.f;

    for (int n0 = 0; n0 < NN; n0 += NT) {
        // ---- fill ks [32][64] fp32, vs [256][64] bf16
#pragma unroll
        for (int i = 0; i < 2; i++) {
            int idx = i * 256 + t;
            int d = idx >> 4, nq = idx & 15;
            *(float4*)&ks[d * 72 + nq * 4] =
                *(const float4*)&g_k[((size_t)(b * DD + d)) * NN + n0 + nq * 4];
        }
#pragma unroll
        for (int it = 0; it < 8; it++) {
            int idx = it * 256 + t;
            int c = idx >> 3, seg = idx & 7;
            *(uint4*)(vs + c * 144 + seg * 16) =
                *(const uint4*)&g_vb[((size_t)(b * CC + c)) * NN + n0 + seg * 8];
        }
        __syncthreads();

        // ---- S: m16 x n64 tf32 (once per row — no duplication)
        float sacc[8][4];
#pragma unroll
        for (int l = 0; l < 8; l++)
#pragma unroll
            for (int j = 0; j < 4; j++) sacc[l][j] = 0.f;
#pragma unroll
        for (int k4 = 0; k4 < 4; k4++) {
            const int kr = k4 * 8;
#pragma unroll
            for (int nt = 0; nt < 8; nt++) {
                int n = nt * 8 + lr;
                uint32_t b0 = __float_as_uint(ks[(kr + lc) * 72 + n]);
                uint32_t b1 = __float_as_uint(ks[(kr + lc + 4) * 72 + n]);
                mma_tf32(sacc[nt], qf[k4], b0, b1);
            }
        }
        // ---- exp (bounded, no max-sub) + psum + pack PV A-frags
        uint32_t pv_a[4][4];
#pragma unroll
        for (int kt = 0; kt < 4; kt++) {
            float e00 = __expf(sacc[2 * kt][0]), e01 = __expf(sacc[2 * kt][1]);
            float e02 = __expf(sacc[2 * kt][2]), e03 = __expf(sacc[2 * kt][3]);
            float e10 = __expf(sacc[2 * kt + 1][0]), e11 = __expf(sacc[2 * kt + 1][1]);
            float e12 = __expf(sacc[2 * kt + 1][2]), e13 = __expf(sacc[2 * kt + 1][3]);
            psum_lo += (e00 + e01) + (e10 + e11);
            psum_hi += (e02 + e03) + (e12 + e13);
            pv_a[kt][0] = pkbf(e00, e01);
            pv_a[kt][1] = pkbf(e02, e03);
            pv_a[kt][2] = pkbf(e10, e11);
            pv_a[kt][3] = pkbf(e12, e13);
        }

        // ---- PV: acc[m16, c256] += P[m16,k64] x V[c256,k64]^T
#pragma unroll
        for (int ntc = 0; ntc < 32; ntc++) {
            uint32_t base = vsb + (ntc * 8 + (lane & 7)) * 144 + ((lane >> 3) * 16);
            uint32_t v0, v1, v2, v3;
            ldsm_x4(v0, v1, v2, v3, base);
            mma_bf16(acc[ntc], pv_a[0], v0, v1);
            mma_bf16(acc[ntc], pv_a[1], v2, v3);
            ldsm_x4(v0, v1, v2, v3, base + 64);
            mma_bf16(acc[ntc], pv_a[2], v0, v1);
            mma_bf16(acc[ntc], pv_a[3], v2, v3);
        }
        __syncthreads();
    }

    // ---- row sums (reduce over lc lanes) -> gri = gamma / psum
    psum_lo += __shfl_xor_sync(0xffffffffu, psum_lo, 1);
    psum_lo += __shfl_xor_sync(0xffffffffu, psum_lo, 2);
    psum_hi += __shfl_xor_sync(0xffffffffu, psum_hi, 1);
    psum_hi += __shfl_xor_sync(0xffffffffu, psum_hi, 2);
    float gamma = gamma_p[0];
    if (lc == 0) {
        gri[w * 16 + lr]     = gamma / psum_lo;
        gri[w * 16 + lr + 8] = gamma / psum_hi;
    }
    __syncthreads();   // all tiles done; obuf overlay begins

    // ---- stage acc into obuf[c][m] (stride 132, conflict-free)
#pragma unroll
    for (int ntc = 0; ntc < 32; ntc++) {
        int c = ntc * 8 + 2 * lc;
        int m = w * 16 + lr;
        obuf[c * 132 + m]           = acc[ntc][0];
        obuf[(c + 1) * 132 + m]     = acc[ntc][1];
        obuf[c * 132 + m + 8]       = acc[ntc][2];
        obuf[(c + 1) * 132 + m + 8] = acc[ntc][3];
    }
    __syncthreads();

    // ---- final: out = obuf * gri + ef, coalesced float4
#pragma unroll
    for (int i = 0; i < 32; i++) {
        int idx = i * 256 + t;
        int c = idx >> 5, mq = idx & 31;
        size_t gi = ((size_t)(b * CC + c)) * NN + m0 + mq * 4;
        float4 e4 = *(const float4*)&ef[gi];
        float4 o4;
        o4.x = obuf[c * 132 + mq * 4 + 0] * gri[mq * 4 + 0] + e4.x;
        o4.y = obuf[c * 132 + mq * 4 + 1] * gri[mq * 4 + 1] + e4.y;
        o4.z = obuf[c * 132 + mq * 4 + 2] * gri[mq * 4 + 2] + e4.z;
        o4.w = obuf[c * 132 + mq * 4 + 3] * gri[mq * 4 + 3] + e4.w;
        *(float4*)&out[gi] = o4;
    }
}

// ---------------------------------------------------------------------------
extern "C" void kernel_launch(void* const* d_in, const int* in_sizes, int n_in,
                              void* d_out, int out_size)
{
    const float* ef = (const float*)d_in[0];
    const float* sf = (const float*)d_in[1];
    const float* At = (const float*)d_in[2];
    const float* Qw = (const float*)d_in[3];
    const float* Qb = (const float*)d_in[4];
    const float* Kw = (const float*)d_in[5];
    const float* Kb = (const float*)d_in[6];
    const float* Vw = (const float*)d_in[7];
    const float* Vb = (const float*)d_in[8];
    const float* gm = (const float*)d_in[9];
    float* out = (float*)d_out;

    float *qp, *kp;
    cudaGetSymbolAddress((void**)&qp, g_q);
    cudaGetSymbolAddress((void**)&kp, g_k);

    cudaFuncSetAttribute(attn_kernel,
                         cudaFuncAttributeMaxDynamicSharedMemorySize, SMEM_ATT);

    wconv_kernel<<<CC * INCH / 1024, 256>>>(Vw);
    projQK_kernel<<<dim3(NN / 128, 1, BN), 256>>>(ef, sf, CC, INCH, Qw, Qb, qp);
    projQK_kernel<<<dim3(NN / 128, 1, BN), 256>>>(At, At, CC, CC, Kw, Kb, kp);
    projV_kernel<<<dim3(NN / 128, CC / 64, BN), 256>>>(ef, sf, Vb);

    attn_kernel<<<dim3(NN / MT, BN), 256, SMEM_ATT>>>(ef, gm, out);
}

// round 12
// speedup vs baseline: 8.1862x; 1.0715x over previous
#include <cuda_runtime.h>
#include <cuda_bf16.h>
#include <math.h>
#include <stdint.h>

#define BN   4
#define CC   256
#define NN   4096
#define DD   32
#define INCH 512

#define MT     128   // query rows per CTA (attn)
#define NT     64    // keys per tile
#define NTILES (NN / NT)

// attn dynamic smem: two (ks,vs) buffers + epilogue overlay
#define KS_SZ   9216                // ks fp32 [32][72]
#define VS_SZ   36864               // vs bf16 [256] rows of 144B
#define BUF_SZ  (KS_SZ + VS_SZ)     // 46080; x2 = 92160
#define SMEM_ATT 135168             // obuf overlay [256][132] fp32 dominates

__device__ float g_q[BN * DD * NN];
__device__ float g_k[BN * DD * NN];
__device__ __nv_bfloat16 g_vb[(size_t)BN * CC * NN];  // [b][c][n] channel-major
__device__ __nv_bfloat16 g_wvb[CC * INCH];            // bf16 V weights

// ---- mma / ldmatrix / cp.async wrappers -----------------------------------
__device__ __forceinline__ void mma_tf32(float* d, const uint32_t* a,
                                         uint32_t b0, uint32_t b1) {
    asm volatile(
        "mma.sync.aligned.m16n8k8.row.col.f32.tf32.tf32.f32 "
        "{%0,%1,%2,%3}, {%4,%5,%6,%7}, {%8,%9}, {%0,%1,%2,%3};"
        : "+f"(d[0]), "+f"(d[1]), "+f"(d[2]), "+f"(d[3])
        : "r"(a[0]), "r"(a[1]), "r"(a[2]), "r"(a[3]), "r"(b0), "r"(b1));
}
__device__ __forceinline__ void mma_bf16(float* d, const uint32_t* a,
                                         uint32_t b0, uint32_t b1) {
    asm volatile(
        "mma.sync.aligned.m16n8k16.row.col.f32.bf16.bf16.f32 "
        "{%0,%1,%2,%3}, {%4,%5,%6,%7}, {%8,%9}, {%0,%1,%2,%3};"
        : "+f"(d[0]), "+f"(d[1]), "+f"(d[2]), "+f"(d[3])
        : "r"(a[0]), "r"(a[1]), "r"(a[2]), "r"(a[3]), "r"(b0), "r"(b1));
}
__device__ __forceinline__ void ldsm_x4(uint32_t& r0, uint32_t& r1,
                                        uint32_t& r2, uint32_t& r3,
                                        uint32_t addr) {
    asm volatile("ldmatrix.sync.aligned.m8n8.x4.shared.b16 {%0,%1,%2,%3}, [%4];"
                 : "=r"(r0), "=r"(r1), "=r"(r2), "=r"(r3) : "r"(addr));
}
__device__ __forceinline__ void ldsm_x4t(uint32_t& r0, uint32_t& r1,
                                         uint32_t& r2, uint32_t& r3,
                                         uint32_t addr) {
    asm volatile("ldmatrix.sync.aligned.m8n8.x4.trans.shared.b16 {%0,%1,%2,%3}, [%4];"
                 : "=r"(r0), "=r"(r1), "=r"(r2), "=r"(r3) : "r"(addr));
}
__device__ __forceinline__ uint32_t smem_u32(const void* p) {
    uint32_t a;
    asm("{ .reg .u64 t; cvta.to.shared.u64 t, %1; cvt.u32.u64 %0, t; }"
        : "=r"(a) : "l"(p));
    return a;
}
__device__ __forceinline__ uint32_t pkbf(float a, float b) {
    __nv_bfloat162 h = __floats2bfloat162_rn(a, b);
    return *(uint32_t*)&h;
}
__device__ __forceinline__ void cpa16(uint32_t dst, const void* src) {
    asm volatile("cp.async.cg.shared.global [%0], [%1], 16;"
                 :: "r"(dst), "l"(src));
}

// ---------------------------------------------------------------------------
// Q/K projection via tf32 HMMA. O=32 out-ch, CTA = 128 px.
// ---------------------------------------------------------------------------
__global__ __launch_bounds__(256) void projQK_kernel(
    const float* __restrict__ x1, const float* __restrict__ x2,
    int C1, int Ctot,
    const float* __restrict__ W, const float* __restrict__ bias,
    float* __restrict__ out)
{
    __shared__ __align__(16) float xs[16 * 136];
    const int m0 = blockIdx.x * 128;
    const int b  = blockIdx.z;
    const int t  = threadIdx.x;
    const int w  = t >> 5, lane = t & 31;
    const int lr = lane >> 2, lc = lane & 3;
    const int wo = w >> 2, wn = w & 3;

    float acc[4][4];
#pragma unroll
    for (int i = 0; i < 4; i++)
#pragma unroll
        for (int j = 0; j < 4; j++) acc[i][j] = 0.f;

    for (int c0 = 0; c0 < Ctot; c0 += 16) {
#pragma unroll
        for (int i = 0; i < 2; i++) {
            int idx = i * 256 + t;
            int r = idx >> 5, c4 = idx & 31;
            int c = c0 + r;
            const float* src = (c < C1)
                ? x1 + ((size_t)b * C1 + c) * NN
                : x2 + ((size_t)b * (Ctot - C1) + (c - C1)) * NN;
            *(float4*)&xs[r * 136 + c4 * 4] = *(const float4*)&src[m0 + c4 * 4];
        }
        __syncthreads();
#pragma unroll
        for (int k8 = 0; k8 < 2; k8++) {
            const float* wr = W + (size_t)(wo * 16 + lr) * Ctot + c0 + k8 * 8;
            uint32_t a[4];
            a[0] = __float_as_uint(wr[lc]);
            a[1] = __float_as_uint(wr[8 * Ctot + lc]);
            a[2] = __float_as_uint(wr[lc + 4]);
            a[3] = __float_as_uint(wr[8 * Ctot + lc + 4]);
#pragma unroll
            for (int nt = 0; nt < 4; nt++) {
                int n = wn * 32 + nt * 8 + lr;
                uint32_t b0 = __float_as_uint(xs[(k8 * 8 + lc) * 136 + n]);
                uint32_t b1 = __float_as_uint(xs[(k8 * 8 + lc + 4) * 136 + n]);
                mma_tf32(acc[nt], a, b0, b1);
            }
        }
        __syncthreads();
    }
    const int o = wo * 16 + lr;
    float bo0 = bias[o], bo1 = bias[o + 8];
#pragma unroll
    for (int nt = 0; nt < 4; nt++) {
        int m = m0 + wn * 32 + nt * 8 + 2 * lc;
        *(float2*)&out[((size_t)(b * 32 + o)) * NN + m] =
            make_float2(acc[nt][0] + bo0, acc[nt][1] + bo0);
        *(float2*)&out[((size_t)(b * 32 + o + 8)) * NN + m] =
            make_float2(acc[nt][2] + bo1, acc[nt][3] + bo1);
    }
}

// ---------------------------------------------------------------------------
// convert V weights fp32 -> bf16 (once)
// ---------------------------------------------------------------------------
__global__ void wconv_kernel(const float* __restrict__ W) {
    int i = (blockIdx.x * 256 + threadIdx.x) * 4;
    float4 v = *(const float4*)&W[i];
    uint2 o = make_uint2(pkbf(v.x, v.y), pkbf(v.z, v.w));
    *(uint2*)&g_wvb[i] = o;
}

// ---------------------------------------------------------------------------
// V projection via bf16 HMMA. CTA = 64 px x ALL 256 out-ch (x read/converted
// once); 8 warps, each owns 2 o16-tiles x m64. grid (NN/64, BN).
// ---------------------------------------------------------------------------
__global__ __launch_bounds__(256) void projV_kernel(
    const float* __restrict__ x1, const float* __restrict__ x2,
    const float* __restrict__ bias)
{
    __shared__ __align__(16) char xs[16 * 144];   // [k16][m64] bf16, 144B rows
    const int m0 = blockIdx.x * 64;
    const int b  = blockIdx.y;
    const int t  = threadIdx.x;
    const int w  = t >> 5, lane = t & 31;
    const int lr = lane >> 2, lc = lane & 3;
    const int obase = w * 32;                     // two o16 tiles per warp
    const uint32_t xsb = smem_u32(xs);

    float acc[2][8][4];
#pragma unroll
    for (int ot = 0; ot < 2; ot++)
#pragma unroll
        for (int i = 0; i < 8; i++)
#pragma unroll
            for (int j = 0; j < 4; j++) acc[ot][i][j] = 0.f;

    const int fk = t >> 4, fm = t & 15;           // fill: k row, px quad

    for (int c0 = 0; c0 < INCH; c0 += 16) {
        {
            int ci = c0 + fk;
            const float* src = (ci < CC)
                ? x1 + ((size_t)b * CC + ci) * NN
                : x2 + ((size_t)b * CC + (ci - CC)) * NN;
            float4 v = *(const float4*)&src[m0 + fm * 4];
            *(uint2*)(xs + fk * 144 + fm * 8) =
                make_uint2(pkbf(v.x, v.y), pkbf(v.z, v.w));
        }
        __syncthreads();
        // A-frags for both o-tiles (W bf16, L2-resident)
        uint32_t a[2][4];
#pragma unroll
        for (int ot = 0; ot < 2; ot++) {
            const __nv_bfloat16* wr =
                g_wvb + (size_t)(obase + ot * 16 + lr) * INCH + c0;
            a[ot][0] = *(const uint32_t*)(wr + 2 * lc);
            a[ot][1] = *(const uint32_t*)(wr + 8 * INCH + 2 * lc);
            a[ot][2] = *(const uint32_t*)(wr + 2 * lc + 8);
            a[ot][3] = *(const uint32_t*)(wr + 8 * INCH + 2 * lc + 8);
        }
        // B-frags shared by both o-tiles
#pragma unroll
        for (int ntp = 0; ntp < 4; ntp++) {
            uint32_t r0, r1, r2, r3;
            uint32_t addr = xsb + ((lane & 7) + ((lane >> 3) & 1) * 8) * 144
                          + ((ntp * 2 + (lane >> 4)) * 8) * 2;
            ldsm_x4t(r0, r1, r2, r3, addr);
            mma_bf16(acc[0][ntp * 2],     a[0], r0, r1);
            mma_bf16(acc[0][ntp * 2 + 1], a[0], r2, r3);
            mma_bf16(acc[1][ntp * 2],     a[1], r0, r1);
            mma_bf16(acc[1][ntp * 2 + 1], a[1], r2, r3);
        }
        __syncthreads();
    }
#pragma unroll
    for (int ot = 0; ot < 2; ot++) {
        const int o = obase + ot * 16 + lr;
        float b0 = bias[o], b1 = bias[o + 8];
#pragma unroll
        for (int nt = 0; nt < 8; nt++) {
            int m = m0 + nt * 8 + 2 * lc;
            size_t gi = ((size_t)(b * CC + o)) * NN + m;
            *(uint32_t*)&g_vb[gi] = pkbf(acc[ot][nt][0] + b0, acc[ot][nt][1] + b0);
            *(uint32_t*)&g_vb[gi + 8 * NN] =
                pkbf(acc[ot][nt][2] + b1, acc[ot][nt][3] + b1);
        }
    }
}

// ---------------------------------------------------------------------------
// Attention FA2: tf32 S (no dup), exp in regs, P reg-chained into bf16 PV.
// K/V tiles double-buffered via cp.async. CTA = 128 rows, 8 warps.
// ---------------------------------------------------------------------------
__global__ __launch_bounds__(256, 1) void attn_kernel(
    const float* __restrict__ ef, const float* __restrict__ gamma_p,
    float* __restrict__ out)
{
    extern __shared__ __align__(16) char smem[];
    const uint32_t sbase = smem_u32(smem);
    float* qs = (float*)smem;              // [k32][m128] stride 132 (pre-loop)
    float* obuf = (float*)smem;            // epilogue overlay [c][m] stride 132
    __shared__ float gri[128];

    const int t = threadIdx.x;
    const int w = t >> 5, lane = t & 31;
    const int lr = lane >> 2, lc = lane & 3;
    const int b  = blockIdx.y;
    const int m0 = blockIdx.x * MT;

    // stage q [32][128], extract resident tf32 A-frags
#pragma unroll
    for (int i = 0; i < 4; i++) {
        int idx = i * 256 + t;
        int d = idx >> 5, mq = idx & 31;
        *(float4*)&qs[d * 132 + mq * 4] =
            *(const float4*)&g_q[((size_t)(b * DD + d)) * NN + m0 + mq * 4];
    }
    __syncthreads();
    uint32_t qf[4][4];
    {
        const int m = w * 16 + lr;
#pragma unroll
        for (int k4 = 0; k4 < 4; k4++) {
            qf[k4][0] = __float_as_uint(qs[(k4 * 8 + lc) * 132 + m]);
            qf[k4][1] = __float_as_uint(qs[(k4 * 8 + lc) * 132 + m + 8]);
            qf[k4][2] = __float_as_uint(qs[(k4 * 8 + lc + 4) * 132 + m]);
            qf[k4][3] = __float_as_uint(qs[(k4 * 8 + lc + 4) * 132 + m + 8]);
        }
    }
    __syncthreads();

    float acc[32][4];
#pragma unroll
    for (int i = 0; i < 32; i++)
#pragma unroll
        for (int j = 0; j < 4; j++) acc[i][j] = 0.f;
    float psum_lo = 0.f, psum_hi = 0.f;

    // ---- prefetch tile 0 into buffer 0
    {
        const int n0 = 0;
        uint32_t ksb = sbase, vsb2 = sbase + KS_SZ;
#pragma unroll
        for (int i = 0; i < 2; i++) {
            int idx = i * 256 + t;
            int d = idx >> 4, nq = idx & 15;
            cpa16(ksb + d * 288 + nq * 16,
                  &g_k[((size_t)(b * DD + d)) * NN + n0 + nq * 4]);
        }
#pragma unroll
        for (int it = 0; it < 8; it++) {
            int idx = it * 256 + t;
            int c = idx >> 3, seg = idx & 7;
            cpa16(vsb2 + c * 144 + seg * 16,
                  &g_vb[((size_t)(b * CC + c)) * NN + n0 + seg * 8]);
        }
        asm volatile("cp.async.commit_group;" ::: "memory");
    }

    for (int ti = 0; ti < NTILES; ti++) {
        const int cur = ti & 1;
        // prefetch next tile into the other buffer (free since prior compute done)
        if (ti + 1 < NTILES) {
            const int n0 = (ti + 1) * NT;
            uint32_t ksb = sbase + (cur ^ 1) * BUF_SZ;
            uint32_t vsb2 = ksb + KS_SZ;
#pragma unroll
            for (int i = 0; i < 2; i++) {
                int idx = i * 256 + t;
                int d = idx >> 4, nq = idx & 15;
                cpa16(ksb + d * 288 + nq * 16,
                      &g_k[((size_t)(b * DD + d)) * NN + n0 + nq * 4]);
            }
#pragma unroll
            for (int it = 0; it < 8; it++) {
                int idx = it * 256 + t;
                int c = idx >> 3, seg = idx & 7;
                cpa16(vsb2 + c * 144 + seg * 16,
                      &g_vb[((size_t)(b * CC + c)) * NN + n0 + seg * 8]);
            }
            asm volatile("cp.async.commit_group;" ::: "memory");
            asm volatile("cp.async.wait_group 1;" ::: "memory");
        } else {
            asm volatile("cp.async.wait_group 0;" ::: "memory");
        }
        __syncthreads();

        const float* ks = (const float*)(smem + cur * BUF_SZ);
        const uint32_t vsb = sbase + cur * BUF_SZ + KS_SZ;

        // ---- S: m16 x n64 tf32 (once per row)
        float sacc[8][4];
#pragma unroll
        for (int l = 0; l < 8; l++)
#pragma unroll
            for (int j = 0; j < 4; j++) sacc[l][j] = 0.f;
#pragma unroll
        for (int k4 = 0; k4 < 4; k4++) {
            const int kr = k4 * 8;
#pragma unroll
            for (int nt = 0; nt < 8; nt++) {
                int n = nt * 8 + lr;
                uint32_t b0 = __float_as_uint(ks[(kr + lc) * 72 + n]);
                uint32_t b1 = __float_as_uint(ks[(kr + lc + 4) * 72 + n]);
                mma_tf32(sacc[nt], qf[k4], b0, b1);
            }
        }
        // ---- exp (bounded, no max-sub) + psum + pack PV A-frags
        uint32_t pv_a[4][4];
#pragma unroll
        for (int kt = 0; kt < 4; kt++) {
            float e00 = __expf(sacc[2 * kt][0]), e01 = __expf(sacc[2 * kt][1]);
            float e02 = __expf(sacc[2 * kt][2]), e03 = __expf(sacc[2 * kt][3]);
            float e10 = __expf(sacc[2 * kt + 1][0]), e11 = __expf(sacc[2 * kt + 1][1]);
            float e12 = __expf(sacc[2 * kt + 1][2]), e13 = __expf(sacc[2 * kt + 1][3]);
            psum_lo += (e00 + e01) + (e10 + e11);
            psum_hi += (e02 + e03) + (e12 + e13);
            pv_a[kt][0] = pkbf(e00, e01);
            pv_a[kt][1] = pkbf(e02, e03);
            pv_a[kt][2] = pkbf(e10, e11);
            pv_a[kt][3] = pkbf(e12, e13);
        }

        // ---- PV: acc[m16, c256] += P[m16,k64] x V[c256,k64]^T
#pragma unroll
        for (int ntc = 0; ntc < 32; ntc++) {
            uint32_t base = vsb + (ntc * 8 + (lane & 7)) * 144 + ((lane >> 3) * 16);
            uint32_t v0, v1, v2, v3;
            ldsm_x4(v0, v1, v2, v3, base);
            mma_bf16(acc[ntc], pv_a[0], v0, v1);
            mma_bf16(acc[ntc], pv_a[1], v2, v3);
            ldsm_x4(v0, v1, v2, v3, base + 64);
            mma_bf16(acc[ntc], pv_a[2], v0, v1);
            mma_bf16(acc[ntc], pv_a[3], v2, v3);
        }
        __syncthreads();
    }

    // ---- row sums -> gri = gamma / psum
    psum_lo += __shfl_xor_sync(0xffffffffu, psum_lo, 1);
    psum_lo += __shfl_xor_sync(0xffffffffu, psum_lo, 2);
    psum_hi += __shfl_xor_sync(0xffffffffu, psum_hi, 1);
    psum_hi += __shfl_xor_sync(0xffffffffu, psum_hi, 2);
    float gamma = gamma_p[0];
    if (lc == 0) {
        gri[w * 16 + lr]     = gamma / psum_lo;
        gri[w * 16 + lr + 8] = gamma / psum_hi;
    }
    __syncthreads();   // tiles dead; obuf overlay begins

    // ---- stage acc into obuf[c][m] (stride 132)
#pragma unroll
    for (int ntc = 0; ntc < 32; ntc++) {
        int c = ntc * 8 + 2 * lc;
        int m = w * 16 + lr;
        obuf[c * 132 + m]           = acc[ntc][0];
        obuf[(c + 1) * 132 + m]     = acc[ntc][1];
        obuf[c * 132 + m + 8]       = acc[ntc][2];
        obuf[(c + 1) * 132 + m + 8] = acc[ntc][3];
    }
    __syncthreads();

    // ---- final: out = obuf * gri + ef, coalesced float4
#pragma unroll
    for (int i = 0; i < 32; i++) {
        int idx = i * 256 + t;
        int c = idx >> 5, mq = idx & 31;
        size_t gi = ((size_t)(b * CC + c)) * NN + m0 + mq * 4;
        float4 e4 = *(const float4*)&ef[gi];
        float4 o4;
        o4.x = obuf[c * 132 + mq * 4 + 0] * gri[mq * 4 + 0] + e4.x;
        o4.y = obuf[c * 132 + mq * 4 + 1] * gri[mq * 4 + 1] + e4.y;
        o4.z = obuf[c * 132 + mq * 4 + 2] * gri[mq * 4 + 2] + e4.z;
        o4.w = obuf[c * 132 + mq * 4 + 3] * gri[mq * 4 + 3] + e4.w;
        *(float4*)&out[gi] = o4;
    }
}

// ---------------------------------------------------------------------------
extern "C" void kernel_launch(void* const* d_in, const int* in_sizes, int n_in,
                              void* d_out, int out_size)
{
    const float* ef = (const float*)d_in[0];
    const float* sf = (const float*)d_in[1];
    const float* At = (const float*)d_in[2];
    const float* Qw = (const float*)d_in[3];
    const float* Qb = (const float*)d_in[4];
    const float* Kw = (const float*)d_in[5];
    const float* Kb = (const float*)d_in[6];
    const float* Vw = (const float*)d_in[7];
    const float* Vb = (const float*)d_in[8];
    const float* gm = (const float*)d_in[9];
    float* out = (float*)d_out;

    float *qp, *kp;
    cudaGetSymbolAddress((void**)&qp, g_q);
    cudaGetSymbolAddress((void**)&kp, g_k);

    cudaFuncSetAttribute(attn_kernel,
                         cudaFuncAttributeMaxDynamicSharedMemorySize, SMEM_ATT);

    wconv_kernel<<<CC * INCH / 1024, 256>>>(Vw);
    projQK_kernel<<<dim3(NN / 128, 1, BN), 256>>>(ef, sf, CC, INCH, Qw, Qb, qp);
    projQK_kernel<<<dim3(NN / 128, 1, BN), 256>>>(At, At, CC, CC, Kw, Kb, kp);
    projV_kernel<<<dim3(NN / 64, BN), 256>>>(ef, sf, Vb);

    attn_kernel<<<dim3(NN / MT, BN), 256, SMEM_ATT>>>(ef, gm, out);
}